// round 10
// baseline (speedup 1.0000x reference)
#include <cuda_runtime.h>
#include <cuda_bf16.h>
#include <cstdint>

#define BB   4
#define SS   2048
#define SKK  2048
#define HH   512
#define NHH  8
#define DSS  64
#define MTOT (BB*SS)            // 8192
#define BATCH_ELEMS (SS*HH)     // 1048576
#define NPART 64
#define EPSN 1e-5f
#define ATTN_SCALE 0.044194173824159216f   // 1/sqrt(512)
#define LOG2E 1.4426950408889634f

#define RS   20   // gemm smem row stride (uints) = 40 bf16 -> ldmatrix conflict-free
#define BSTU 36   // attn smem row stride (uints) = 72 bf16 -> conflict-free
#define ASTG 4    // attention pipeline stages

// ---------------- scratch (static device memory; no allocations) ----------------
__device__ __nv_bfloat16 g_Xq[MTOT*HH];    // normed Q input, bf16
__device__ __nv_bfloat16 g_Xk[MTOT*HH];    // normed K input, bf16
__device__ __nv_bfloat16 g_XoH[MTOT*HH];   // normed O1, bf16 hi
__device__ __nv_bfloat16 g_XoL[MTOT*HH];   // normed O1, bf16 lo
__device__ __nv_bfloat16 g_pQh[MTOT*HH];   // pQ * ATTN_SCALE * log2(e), [m][d]
__device__ __nv_bfloat16 g_pKh[MTOT*HH];   // [m][d]
__device__ __nv_bfloat16 g_pVh[MTOT*HH];   // [m][d]
__device__ float g_O1[MTOT*HH];
__device__ __nv_bfloat16 g_wqh[HH*HH], g_wkh[HH*HH], g_wvh[HH*HH];
__device__ __nv_bfloat16 g_wch[HH*HH], g_wcl[HH*HH];
__device__ float g_part[2][BB][NPART][2];   // Q/K input partial sums
__device__ float g_apart[BB][NHH*16][2];    // O1 partial sums (from attention blocks)

// ---------------- helpers ----------------
__device__ __forceinline__ unsigned packbf(float lo, float hi){
    unsigned r; asm("cvt.rn.bf16x2.f32 %0, %1, %2;" : "=r"(r) : "f"(hi), "f"(lo)); return r;
}
__device__ __forceinline__ float ex2f(float x){
    float y; asm("ex2.approx.ftz.f32 %0, %1;" : "=f"(y) : "f"(x)); return y;
}
__device__ __forceinline__ void mma_bf16(float c[4], const unsigned a[4], const unsigned b[2]){
    asm volatile("mma.sync.aligned.m16n8k16.row.col.f32.bf16.bf16.f32 "
        "{%0,%1,%2,%3}, {%4,%5,%6,%7}, {%8,%9}, {%0,%1,%2,%3};"
        : "+f"(c[0]), "+f"(c[1]), "+f"(c[2]), "+f"(c[3])
        : "r"(a[0]), "r"(a[1]), "r"(a[2]), "r"(a[3]), "r"(b[0]), "r"(b[1]));
}
__device__ __forceinline__ void ldm_x4(unsigned r[4], uint32_t addr){
    asm volatile("ldmatrix.sync.aligned.m8n8.x4.shared.b16 {%0,%1,%2,%3}, [%4];"
        : "=r"(r[0]), "=r"(r[1]), "=r"(r[2]), "=r"(r[3]) : "r"(addr));
}
__device__ __forceinline__ void ldm_x4_t(unsigned r[4], uint32_t addr){
    asm volatile("ldmatrix.sync.aligned.m8n8.x4.trans.shared.b16 {%0,%1,%2,%3}, [%4];"
        : "=r"(r[0]), "=r"(r[1]), "=r"(r[2]), "=r"(r[3]) : "r"(addr));
}
__device__ __forceinline__ void cp16(uint32_t dst, const void* src){
    asm volatile("cp.async.ca.shared.global [%0], [%1], 16;" :: "r"(dst), "l"(src));
}
__device__ __forceinline__ void cp_commit(){
    asm volatile("cp.async.commit_group;");
}

// ---------------- prep: convert weights to bf16 + input stats, one launch ----------------
// grid.x: [0,256) convert_w, [256,512) reduce Q slot0, [512,768) reduce K slot1
__global__ void __launch_bounds__(256) prep_kernel(
    const float* __restrict__ Q, const float* __restrict__ K,
    const float* __restrict__ wq, const float* __restrict__ wk,
    const float* __restrict__ wv, const float* __restrict__ wc)
{
    __shared__ float ss[8], sq[8];
    const int bx = blockIdx.x, t = threadIdx.x;
    if (bx < 256){
        const int i = bx * 256 + t;   // quad index < 65536
        {
            float4 v = ((const float4*)wq)[i];
            ((uint2*)(unsigned*)g_wqh)[i] = make_uint2(packbf(v.x, v.y), packbf(v.z, v.w));
        }
        {
            float4 v = ((const float4*)wk)[i];
            ((uint2*)(unsigned*)g_wkh)[i] = make_uint2(packbf(v.x, v.y), packbf(v.z, v.w));
        }
        {
            float4 v = ((const float4*)wv)[i];
            ((uint2*)(unsigned*)g_wvh)[i] = make_uint2(packbf(v.x, v.y), packbf(v.z, v.w));
        }
        {
            float4 v = ((const float4*)wc)[i];
            unsigned h0 = packbf(v.x, v.y), h1 = packbf(v.z, v.w);
            ((uint2*)(unsigned*)g_wch)[i] = make_uint2(h0, h1);
            float hx = __uint_as_float(h0 << 16), hy = __uint_as_float(h0 & 0xffff0000u);
            float hz = __uint_as_float(h1 << 16), hw = __uint_as_float(h1 & 0xffff0000u);
            ((uint2*)(unsigned*)g_wcl)[i] = make_uint2(packbf(v.x - hx, v.y - hy), packbf(v.z - hz, v.w - hw));
        }
        return;
    }
    const int slot = (bx >= 512) ? 1 : 0;
    const int idx = bx - 256 - slot*256;
    const int batch = idx >> 6, part = idx & 63;
    const float* x = slot ? K : Q;
    const float4* p = (const float4*)(x + (size_t)batch*BATCH_ELEMS + (size_t)part*(BATCH_ELEMS/NPART));
    float s = 0.f, q = 0.f;
#pragma unroll
    for (int i = 0; i < 16; i++){
        float4 v = p[t + 256*i];
        s += v.x + v.y + v.z + v.w;
        q += v.x*v.x + v.y*v.y + v.z*v.z + v.w*v.w;
    }
#pragma unroll
    for (int off = 16; off; off >>= 1){
        s += __shfl_xor_sync(0xffffffffu, s, off);
        q += __shfl_xor_sync(0xffffffffu, q, off);
    }
    const int w = t >> 5;
    if ((t & 31) == 0){ ss[w] = s; sq[w] = q; }
    __syncthreads();
    if (t == 0){
        float S_ = 0.f, Q_ = 0.f;
#pragma unroll
        for (int i = 0; i < 8; i++){ S_ += ss[i]; Q_ += sq[i]; }
        g_part[slot][batch][part][0] = S_;
        g_part[slot][batch][part][1] = Q_;
    }
}

// ---------------- norm Q/K inputs -> bf16 (stats folded in) ----------------
// grid 8192: bx<4096 -> Q slot0 -> g_Xq; else K slot1 -> g_Xk
__global__ void __launch_bounds__(256) norm_qk(
    const float* __restrict__ Q, const float* __restrict__ K,
    const float* __restrict__ gq, const float* __restrict__ bq,
    const float* __restrict__ gk, const float* __restrict__ bk)
{
    __shared__ float sred[4], smr[2];
    const int tid = threadIdx.x;
    const int slot = (blockIdx.x >= 4096) ? 1 : 0;
    const int i = (blockIdx.x - slot*4096) * 256 + tid;   // quad index < 1048576
    const int batch = i >> 18;
    if (tid < 64){
        float s = g_part[slot][batch][tid][0];
        float q = g_part[slot][batch][tid][1];
#pragma unroll
        for (int off = 16; off; off >>= 1){
            s += __shfl_xor_sync(0xffffffffu, s, off);
            q += __shfl_xor_sync(0xffffffffu, q, off);
        }
        if ((tid & 31) == 0){ sred[(tid>>5)*2] = s; sred[(tid>>5)*2+1] = q; }
    }
    __syncthreads();
    if (tid == 0){
        float S = sred[0] + sred[2], Qa = sred[1] + sred[3];
        float mean = S * (1.0f/(float)BATCH_ELEMS);
        float var  = Qa * (1.0f/(float)BATCH_ELEMS) - mean*mean;
        smr[0] = mean; smr[1] = rsqrtf(var + EPSN);
    }
    __syncthreads();
    const float mean = smr[0], rstd = smr[1];

    const float* X = slot ? K : Q;
    const float* gg = slot ? gk : gq;
    const float* bb = slot ? bk : bq;
    unsigned* outHi = slot ? (unsigned*)g_Xk : (unsigned*)g_Xq;
    const int kq = i & 127;
    const float4 x = ((const float4*)X)[i];
    const float4 g4 = ((const float4*)gg)[kq];
    const float4 b4 = ((const float4*)bb)[kq];
    float4 y;
    y.x = (x.x - mean)*rstd*g4.x + b4.x;
    y.y = (x.y - mean)*rstd*g4.y + b4.y;
    y.z = (x.z - mean)*rstd*g4.z + b4.z;
    y.w = (x.w - mean)*rstd*g4.w + b4.w;
    ((uint2*)outHi)[i] = make_uint2(packbf(y.x, y.y), packbf(y.z, y.w));
}

// ---------------- norm O1 -> bf16 hi/lo (stats from attention partials) ----------------
__global__ void __launch_bounds__(256) norm_o1(
    const float* __restrict__ O1,
    const float* __restrict__ g0, const float* __restrict__ beta0)
{
    __shared__ float sred[8], smr[2];
    const int tid = threadIdx.x;
    const int i = blockIdx.x * 256 + tid;
    const int batch = i >> 18;
    if (tid < 128){
        float s = g_apart[batch][tid][0];
        float q = g_apart[batch][tid][1];
#pragma unroll
        for (int off = 16; off; off >>= 1){
            s += __shfl_xor_sync(0xffffffffu, s, off);
            q += __shfl_xor_sync(0xffffffffu, q, off);
        }
        if ((tid & 31) == 0){ sred[(tid>>5)*2] = s; sred[(tid>>5)*2+1] = q; }
    }
    __syncthreads();
    if (tid == 0){
        float S = sred[0] + sred[2] + sred[4] + sred[6];
        float Qa = sred[1] + sred[3] + sred[5] + sred[7];
        float mean = S * (1.0f/(float)BATCH_ELEMS);
        float var  = Qa * (1.0f/(float)BATCH_ELEMS) - mean*mean;
        smr[0] = mean; smr[1] = rsqrtf(var + EPSN);
    }
    __syncthreads();
    const float mean = smr[0], rstd = smr[1];

    const int kq = i & 127;
    const float4 x = ((const float4*)O1)[i];
    const float4 g4 = ((const float4*)g0)[kq];
    const float4 b4 = ((const float4*)beta0)[kq];
    float4 y;
    y.x = (x.x - mean)*rstd*g4.x + b4.x;
    y.y = (x.y - mean)*rstd*g4.y + b4.y;
    y.z = (x.z - mean)*rstd*g4.z + b4.z;
    y.w = (x.w - mean)*rstd*g4.w + b4.w;
    unsigned h0 = packbf(y.x, y.y), h1 = packbf(y.z, y.w);
    ((uint2*)(unsigned*)g_XoH)[i] = make_uint2(h0, h1);
    float hx = __uint_as_float(h0 << 16), hy = __uint_as_float(h0 & 0xffff0000u);
    float hz = __uint_as_float(h1 << 16), hw = __uint_as_float(h1 & 0xffff0000u);
    ((uint2*)(unsigned*)g_XoL)[i] = make_uint2(packbf(y.x - hx, y.y - hy), packbf(y.z - hz, y.w - hw));
}

// ---------------- fused Q/K/V projection GEMM, 3-stage cp.async ----------------
__global__ void __launch_bounds__(256, 2) gemm_proj(
    const float* __restrict__ bq, const float* __restrict__ bk, const float* __restrict__ bv)
{
    extern __shared__ unsigned smu[];
    unsigned* As = smu;                      // [3][128][RS]
    unsigned* Ws = smu + 3*128*RS;
    const uint32_t sA = (uint32_t)__cvta_generic_to_shared(As);
    const uint32_t sW = (uint32_t)__cvta_generic_to_shared(Ws);

    const int tid  = threadIdx.x;
    const int lane = tid & 31, w = tid >> 5;
    const int g = lane >> 2, t4 = lane & 3;
    const int which = blockIdx.x >> 2;
    const __nv_bfloat16* A = (which == 0) ? g_Xq : g_Xk;
    const __nv_bfloat16* W = (which == 0) ? g_wqh : (which == 1) ? g_wkh : g_wvh;
    const float* biasp = (which == 0) ? bq : (which == 1) ? bk : bv;
    __nv_bfloat16* outp = (which == 0) ? g_pQh : (which == 1) ? g_pKh : g_pVh;
    const float scl = (which == 0) ? (ATTN_SCALE * LOG2E) : 1.0f;
    const int n0 = (blockIdx.x & 3) * 128;
    const int m0 = blockIdx.y * 128;

    const int mw = w >> 1, nw = w & 1;
    const int mrow = mw * 32, nrow = nw * 64;

    float acc[2][8][4];
#pragma unroll
    for (int i = 0; i < 2; i++)
#pragma unroll
        for (int j = 0; j < 8; j++)
#pragma unroll
            for (int r = 0; r < 4; r++) acc[i][j][r] = 0.f;

    const int aRow  = lane & 15;
    const int aColU = (lane >> 4) << 2;
    const int bRow  = ((lane >> 4) << 3) + (lane & 7);
    const int bColU = ((lane >> 3) & 1) << 2;

    auto loadTile = [&](int kt, int s){
        const int kb = kt * 32;
#pragma unroll
        for (int i = 0; i < 2; i++){
            const int c = tid + 256*i;
            const int row = c >> 2, seg = c & 3;
            cp16(sA + (uint32_t)(s*128*RS + row*RS + seg*4)*4, A + (size_t)(m0 + row)*HH + kb + seg*8);
            cp16(sW + (uint32_t)(s*128*RS + row*RS + seg*4)*4, W + (size_t)(n0 + row)*HH + kb + seg*8);
        }
    };

    loadTile(0, 0); cp_commit();
    loadTile(1, 1); cp_commit();

    for (int kt = 0; kt < 16; kt++){
        const int s = kt % 3;
        if (kt + 2 < 16) loadTile(kt + 2, (kt + 2) % 3);
        cp_commit();
        asm volatile("cp.async.wait_group 2;");
        __syncthreads();

        const uint32_t aBase = sA + (uint32_t)(s*128*RS)*4;
        const uint32_t wBase = sW + (uint32_t)(s*128*RS)*4;
#pragma unroll
        for (int ks = 0; ks < 2; ks++){
            unsigned ah[2][4];
#pragma unroll
            for (int i = 0; i < 2; i++)
                ldm_x4(ah[i], aBase + (uint32_t)((mrow + i*16 + aRow)*RS + ks*8 + aColU)*4);
            unsigned bh[4][4];
#pragma unroll
            for (int jj = 0; jj < 4; jj++)
                ldm_x4(bh[jj], wBase + (uint32_t)((nrow + jj*16 + bRow)*RS + ks*8 + bColU)*4);
#pragma unroll
            for (int i = 0; i < 2; i++)
#pragma unroll
                for (int jj = 0; jj < 4; jj++){
                    mma_bf16(acc[i][2*jj],   ah[i], bh[jj]);
                    mma_bf16(acc[i][2*jj+1], ah[i], bh[jj] + 2);
                }
        }
        __syncthreads();
    }

#pragma unroll
    for (int i = 0; i < 2; i++){
#pragma unroll
        for (int j = 0; j < 8; j++){
            const int col = n0 + nrow + j*8 + 2*t4;
            const float2 bs = *(const float2*)&biasp[col];
#pragma unroll
            for (int hh = 0; hh < 2; hh++){
                const int row = m0 + mrow + i*16 + g + 8*hh;
                float cx = acc[i][j][2*hh]   + bs.x;
                float cy = acc[i][j][2*hh+1] + bs.y;
                ((unsigned*)outp)[(size_t)row*(HH/2) + (col >> 1)] = packbf(cx*scl, cy*scl);
            }
        }
    }
}

// ---------------- final GEMM: out = res + relu(A.W^T + bias), 3-term bf16 split ----------------
__global__ void __launch_bounds__(256, 1) gemm_final(
    const float* __restrict__ bc, float* __restrict__ out, const float* __restrict__ res)
{
    extern __shared__ unsigned smu[];
    const int AROWS = 256;
    unsigned* As = smu;                      // [3][256][RS]
    unsigned* Ws = smu + 3*AROWS*RS;
    const uint32_t sA = (uint32_t)__cvta_generic_to_shared(As);
    const uint32_t sW = (uint32_t)__cvta_generic_to_shared(Ws);

    const int tid  = threadIdx.x;
    const int lane = tid & 31, w = tid >> 5;
    const int g = lane >> 2, t4 = lane & 3;
    const int n0 = (int)blockIdx.x * 128;
    const int m0 = blockIdx.y * 128;

    const int mw = w >> 1, nw = w & 1;
    const int mrow = mw * 32, nrow = nw * 64;

    float acc[2][8][4];
#pragma unroll
    for (int i = 0; i < 2; i++)
#pragma unroll
        for (int j = 0; j < 8; j++)
#pragma unroll
            for (int r = 0; r < 4; r++) acc[i][j][r] = 0.f;

    const int aRow  = lane & 15;
    const int aColU = (lane >> 4) << 2;
    const int bRow  = ((lane >> 4) << 3) + (lane & 7);
    const int bColU = ((lane >> 3) & 1) << 2;

    auto loadTile = [&](int kt, int s){
        const int kb = kt * 32;
#pragma unroll
        for (int i = 0; i < 4; i++){
            const int c = tid + 256*i;
            const int row = c >> 2, seg = c & 3;
            const __nv_bfloat16* srcA = (row >= 128)
                ? (g_XoL + (size_t)(m0 + row - 128)*HH + kb + seg*8)
                : (g_XoH + (size_t)(m0 + row)*HH + kb + seg*8);
            cp16(sA + (uint32_t)(s*AROWS*RS + row*RS + seg*4)*4, srcA);
            const __nv_bfloat16* srcW = (row >= 128)
                ? (g_wcl + (size_t)(n0 + row - 128)*HH + kb + seg*8)
                : (g_wch + (size_t)(n0 + row)*HH + kb + seg*8);
            cp16(sW + (uint32_t)(s*AROWS*RS + row*RS + seg*4)*4, srcW);
        }
    };

    loadTile(0, 0); cp_commit();
    loadTile(1, 1); cp_commit();

    for (int kt = 0; kt < 16; kt++){
        const int s = kt % 3;
        if (kt + 2 < 16) loadTile(kt + 2, (kt + 2) % 3);
        cp_commit();
        asm volatile("cp.async.wait_group 2;");
        __syncthreads();

        const uint32_t aBase = sA + (uint32_t)(s*AROWS*RS)*4;
        const uint32_t wBase = sW + (uint32_t)(s*AROWS*RS)*4;
#pragma unroll
        for (int ks = 0; ks < 2; ks++){
            unsigned ah[2][4], alo_[2][4];
#pragma unroll
            for (int i = 0; i < 2; i++){
                ldm_x4(ah[i],   aBase + (uint32_t)((mrow + i*16 + aRow)*RS + ks*8 + aColU)*4);
                ldm_x4(alo_[i], aBase + (uint32_t)((128 + mrow + i*16 + aRow)*RS + ks*8 + aColU)*4);
            }
            unsigned bh[4][4], bl[4][4];
#pragma unroll
            for (int jj = 0; jj < 4; jj++){
                ldm_x4(bh[jj], wBase + (uint32_t)((nrow + jj*16 + bRow)*RS + ks*8 + bColU)*4);
                ldm_x4(bl[jj], wBase + (uint32_t)((128 + nrow + jj*16 + bRow)*RS + ks*8 + bColU)*4);
            }
#pragma unroll
            for (int i = 0; i < 2; i++)
#pragma unroll
                for (int jj = 0; jj < 4; jj++){
                    mma_bf16(acc[i][2*jj],   ah[i], bh[jj]);
                    mma_bf16(acc[i][2*jj+1], ah[i], bh[jj] + 2);
                    mma_bf16(acc[i][2*jj],   ah[i], bl[jj]);
                    mma_bf16(acc[i][2*jj+1], ah[i], bl[jj] + 2);
                    mma_bf16(acc[i][2*jj],   alo_[i], bh[jj]);
                    mma_bf16(acc[i][2*jj+1], alo_[i], bh[jj] + 2);
                }
        }
        __syncthreads();
    }

#pragma unroll
    for (int i = 0; i < 2; i++){
#pragma unroll
        for (int j = 0; j < 8; j++){
            const int col = n0 + nrow + j*8 + 2*t4;
            const float2 bs = *(const float2*)&bc[col];
#pragma unroll
            for (int hh = 0; hh < 2; hh++){
                const int row = m0 + mrow + i*16 + g + 8*hh;
                float cx = acc[i][j][2*hh]   + bs.x;
                float cy = acc[i][j][2*hh+1] + bs.y;
                const float2 rv = *(const float2*)&res[(size_t)row*HH + col];
                float2 o;
                o.x = rv.x + fmaxf(cx, 0.f);
                o.y = rv.y + fmaxf(cy, 0.f);
                *(float2*)&out[(size_t)row*HH + col] = o;
            }
        }
    }
}

// ---------------- flash attention: interleaved S/ex2/PV per 16-key group ----------------
// No-max softmax (P = 2^s) => per-key-group pipeline, tiny sacc live range, and l is a
// plain sum: per-thread partial accumulated in regs, quad-shuffled ONCE in the epilogue.
// 128-thr blocks, 3 blocks/SM; warp owns 32 q-rows x 64 keys; 4-stage cp.async,
// 1 sync per 2 key-tiles.
__global__ void __launch_bounds__(128, 3) attn_mma(
    const float* __restrict__ Qraw, float* __restrict__ O1)
{
    extern __shared__ unsigned smu[];
    unsigned* KsBase = smu;                  // [ASTG][64][BSTU]
    unsigned* VsBase = smu + ASTG*64*BSTU;   // [ASTG][64][BSTU]
    unsigned* Qs     = smu;                  // staging alias (dead after frag extraction)
    __shared__ float sb[4][2];

    const int tid  = threadIdx.x;
    const int lane = tid & 31, w = tid >> 5;   // w in 0..3
    const int g = lane >> 2, t4 = lane & 3;

    const int qt = blockIdx.x, h = blockIdx.y, b = blockIdx.z;
    const int hoff = h * DSS;
    const int qrow0 = b * SS + qt * 128;

    const uint32_t smemK = (uint32_t)__cvta_generic_to_shared(KsBase);
    const uint32_t smemV = (uint32_t)__cvta_generic_to_shared(VsBase);
    const uint32_t smemQ = (uint32_t)__cvta_generic_to_shared(Qs);

    // ---- stage Q tile (cp.async), extract both 16-row A-frag groups
    {
#pragma unroll
        for (int i = 0; i < 8; i++){
            const int ch = tid + 128*i;          // 1024 chunks: 128 rows x 8 segs
            const int row = ch >> 3, c = ch & 7;
            cp16(smemQ + (uint32_t)(row*BSTU + c*4)*4, g_pQh + (size_t)(qrow0 + row)*HH + hoff + c*8);
        }
        cp_commit();
        asm volatile("cp.async.wait_group 0;");
    }
    __syncthreads();

    unsigned q[2][4][4];
    {
        const int aRow = lane & 15, aColU = (lane >> 4) << 2;
#pragma unroll
        for (int hh = 0; hh < 2; hh++)
#pragma unroll
            for (int kc = 0; kc < 4; kc++)
                ldm_x4(q[hh][kc], smemQ + (uint32_t)((w*32 + hh*16 + aRow)*BSTU + kc*8 + aColU)*4);
    }
    __syncthreads();   // Qs dead; K/V pipeline reuses the memory

    float o[2][8][4];
#pragma unroll
    for (int hh = 0; hh < 2; hh++)
#pragma unroll
        for (int j = 0; j < 8; j++)
#pragma unroll
            for (int r = 0; r < 4; r++) o[hh][j][r] = 0.f;
    float lv[4];   // per-thread partial row sums (quad-reduced in epilogue)
#pragma unroll
    for (int r = 0; r < 4; r++) lv[r] = 0.f;

    const __nv_bfloat16* gK0 = g_pKh + ((size_t)b * SKK) * HH + hoff;
    const __nv_bfloat16* gV0 = g_pVh + ((size_t)b * SKK) * HH + hoff;

    auto loadKV = [&](int t, int s){
        const __nv_bfloat16* gK = gK0 + (size_t)t*64*HH;
        const __nv_bfloat16* gV = gV0 + (size_t)t*64*HH;
#pragma unroll
        for (int i = 0; i < 4; i++){
            const int ch = tid + 128*i;          // 512 chunks: 64 rows x 8 segs
            const int row = ch >> 3, c = ch & 7;
            cp16(smemK + (uint32_t)(s*64*BSTU + row*BSTU + c*4)*4, gK + (size_t)row*HH + c*8);
            cp16(smemV + (uint32_t)(s*64*BSTU + row*BSTU + c*4)*4, gV + (size_t)row*HH + c*8);
        }
    };

    loadKV(0, 0); cp_commit();
    loadKV(1, 1); cp_commit();

    const int kRow  = lane & 7;
    const int kColU = (lane >> 3) << 2;
    const int vRow  = lane & 15;
    const int vColU = (lane >> 4) << 2;

    for (int tt = 0; tt < SKK/64; tt += 2){
        // tiles tt, tt+1 are the only pending groups -> drain, then one barrier
        asm volatile("cp.async.wait_group 0;");
        __syncthreads();   // also protects stages (tt+2)&3, (tt+3)&3 (consumed last iter)
        if (tt + 2 < SKK/64){ loadKV(tt + 2, (tt + 2) & (ASTG-1)); cp_commit(); }
        if (tt + 3 < SKK/64){ loadKV(tt + 3, (tt + 3) & (ASTG-1)); cp_commit(); }

#pragma unroll
        for (int u = 0; u < 2; u++){
            const int s = (tt + u) & (ASTG-1);
            const uint32_t kBase = smemK + (uint32_t)(s*64*BSTU)*4;
            const uint32_t vBase = smemV + (uint32_t)(s*64*BSTU)*4;

            // per 16-key group: S-MMAs -> V ldm -> ex2 -> pack -> PV-MMAs
#pragma unroll
            for (int kg = 0; kg < 4; kg++){
                // K fragments for key columns kg*16..kg*16+15 (j tiles 2kg, 2kg+1)
                unsigned kb[4][4];
                ldm_x4(kb[0], kBase + (uint32_t)(((2*kg  )*8 + kRow)*BSTU + kColU)*4);
                ldm_x4(kb[1], kBase + (uint32_t)(((2*kg  )*8 + kRow)*BSTU + 16 + kColU)*4);
                ldm_x4(kb[2], kBase + (uint32_t)(((2*kg+1)*8 + kRow)*BSTU + kColU)*4);
                ldm_x4(kb[3], kBase + (uint32_t)(((2*kg+1)*8 + kRow)*BSTU + 16 + kColU)*4);

                float sc[2][2][4];
#pragma unroll
                for (int hh = 0; hh < 2; hh++)
#pragma unroll
                    for (int jj = 0; jj < 2; jj++)
#pragma unroll
                        for (int r = 0; r < 4; r++) sc[hh][jj][r] = 0.f;

#pragma unroll
                for (int hh = 0; hh < 2; hh++)
#pragma unroll
                    for (int jj = 0; jj < 2; jj++){
                        mma_bf16(sc[hh][jj], q[hh][0], kb[jj*2]);
                        mma_bf16(sc[hh][jj], q[hh][1], kb[jj*2] + 2);
                        mma_bf16(sc[hh][jj], q[hh][2], kb[jj*2+1]);
                        mma_bf16(sc[hh][jj], q[hh][3], kb[jj*2+1] + 2);
                    }

                // V fragments (independent of S results — overlaps MUFU below)
                unsigned vb[4][4];
#pragma unroll
                for (int jp = 0; jp < 4; jp++)
                    ldm_x4_t(vb[jp], vBase + (uint32_t)((kg*16 + vRow)*BSTU + jp*8 + vColU)*4);

                // P = 2^s, per-thread partial l, pack to A-frag
                unsigned pa[2][4];
#pragma unroll
                for (int hh = 0; hh < 2; hh++){
#pragma unroll
                    for (int jj = 0; jj < 2; jj++){
                        sc[hh][jj][0] = ex2f(sc[hh][jj][0]);
                        sc[hh][jj][1] = ex2f(sc[hh][jj][1]);
                        sc[hh][jj][2] = ex2f(sc[hh][jj][2]);
                        sc[hh][jj][3] = ex2f(sc[hh][jj][3]);
                    }
                    lv[hh*2]   += sc[hh][0][0] + sc[hh][0][1] + sc[hh][1][0] + sc[hh][1][1];
                    lv[hh*2+1] += sc[hh][0][2] + sc[hh][0][3] + sc[hh][1][2] + sc[hh][1][3];
                    pa[hh][0] = packbf(sc[hh][0][0], sc[hh][0][1]);
                    pa[hh][1] = packbf(sc[hh][0][2], sc[hh][0][3]);
                    pa[hh][2] = packbf(sc[hh][1][0], sc[hh][1][1]);
                    pa[hh][3] = packbf(sc[hh][1][2], sc[hh][1][3]);
                }

                // O += P V
#pragma unroll
                for (int jp = 0; jp < 4; jp++)
#pragma unroll
                    for (int hh = 0; hh < 2; hh++){
                        mma_bf16(o[hh][2*jp],   pa[hh], vb[jp]);
                        mma_bf16(o[hh][2*jp+1], pa[hh], vb[jp] + 2);
                    }
            }
        }
    }

    // ---- deferred l reduction (quad lanes hold disjoint column partials)
#pragma unroll
    for (int r = 0; r < 4; r++){
        lv[r] += __shfl_xor_sync(0xffffffffu, lv[r], 1);
        lv[r] += __shfl_xor_sync(0xffffffffu, lv[r], 2);
    }

    // ---- epilogue: O1 = Qraw + O / l, with fused sum/sumsq for set-norm stats
    float s1 = 0.f, s2 = 0.f;
#pragma unroll
    for (int hh = 0; hh < 2; hh++){
        const float inv0 = 1.0f / lv[hh*2], inv1 = 1.0f / lv[hh*2+1];
        const int row0 = qrow0 + w*32 + hh*16 + g;
#pragma unroll
        for (int jd = 0; jd < 8; jd++){
            const int col = hoff + jd*8 + 2*t4;
            {
                const float2 qv = *(const float2*)&Qraw[(size_t)row0*HH + col];
                float2 ov; ov.x = qv.x + o[hh][jd][0]*inv0; ov.y = qv.y + o[hh][jd][1]*inv0;
                *(float2*)&O1[(size_t)row0*HH + col] = ov;
                s1 += ov.x + ov.y; s2 += ov.x*ov.x + ov.y*ov.y;
            }
            {
                const float2 qv = *(const float2*)&Qraw[(size_t)(row0+8)*HH + col];
                float2 ov; ov.x = qv.x + o[hh][jd][2]*inv1; ov.y = qv.y + o[hh][jd][3]*inv1;
                *(float2*)&O1[(size_t)(row0+8)*HH + col] = ov;
                s1 += ov.x + ov.y; s2 += ov.x*ov.x + ov.y*ov.y;
            }
        }
    }
#pragma unroll
    for (int off = 16; off; off >>= 1){
        s1 += __shfl_xor_sync(0xffffffffu, s1, off);
        s2 += __shfl_xor_sync(0xffffffffu, s2, off);
    }
    if (lane == 0){ sb[w][0] = s1; sb[w][1] = s2; }
    __syncthreads();
    if (tid == 0){
        float a = 0.f, c = 0.f;
#pragma unroll
        for (int i = 0; i < 4; i++){ a += sb[i][0]; c += sb[i][1]; }
        g_apart[b][h*16 + qt][0] = a;
        g_apart[b][h*16 + qt][1] = c;
    }
}

// ---------------- launcher ----------------
extern "C" void kernel_launch(void* const* d_in, const int* in_sizes, int n_in,
                              void* d_out, int out_size)
{
    (void)in_sizes; (void)n_in; (void)out_size;
    const float* Q     = (const float*)d_in[0];
    const float* K     = (const float*)d_in[1];
    const float* wq    = (const float*)d_in[2];
    const float* bq    = (const float*)d_in[3];
    const float* wk    = (const float*)d_in[4];
    const float* bk    = (const float*)d_in[5];
    const float* wv    = (const float*)d_in[6];
    const float* bv    = (const float*)d_in[7];
    const float* wc    = (const float*)d_in[8];
    const float* bc    = (const float*)d_in[9];
    const float* gq    = (const float*)d_in[10];
    const float* betaq = (const float*)d_in[11];
    const float* gk    = (const float*)d_in[12];
    const float* betak = (const float*)d_in[13];
    const float* g0    = (const float*)d_in[14];
    const float* beta0 = (const float*)d_in[15];
    float* out = (float*)d_out;

    float* O1p;
    cudaGetSymbolAddress((void**)&O1p, g_O1);

    const int PROJ_SMEM = 3 * 2 * 128 * RS * 4;      // 61440
    const int FIN_SMEM  = 3 * 2 * 256 * RS * 4;      // 122880
    const int ATTN_SMEM = 2 * ASTG * 64 * BSTU * 4;  // 73728

    cudaFuncSetAttribute(gemm_proj,  cudaFuncAttributeMaxDynamicSharedMemorySize, PROJ_SMEM);
    cudaFuncSetAttribute(gemm_final, cudaFuncAttributeMaxDynamicSharedMemorySize, FIN_SMEM);
    cudaFuncSetAttribute(attn_mma,   cudaFuncAttributeMaxDynamicSharedMemorySize, ATTN_SMEM);

    // 1. weights->bf16 + Q/K input stats
    prep_kernel<<<768, 256>>>(Q, K, wq, wk, wv, wc);
    // 2. normed inputs -> bf16 (stats folded in)
    norm_qk<<<8192, 256>>>(Q, K, gq, betaq, gk, betak);
    // 3. Q/K/V projections, one launch
    gemm_proj<<<dim3(12, 64), 256, PROJ_SMEM>>>(bq, bk, bv);
    // 4. attention + residual + fused O1 stats
    attn_mma<<<dim3(SS/128, NHH, BB), 128, ATTN_SMEM>>>(Q, O1p);
    // 5. norm O1 -> bf16 hi/lo (stats from attention partials)
    norm_o1<<<4096, 256>>>(O1p, g0, beta0);
    // 6. out = O1 + relu(norm(O1) @ wc^T + bc)
    gemm_final<<<dim3(4, 64), 256, FIN_SMEM>>>(bc, out, O1p);
}

// round 11
// speedup vs baseline: 1.1035x; 1.1035x over previous
#include <cuda_runtime.h>
#include <cuda_bf16.h>
#include <cstdint>

#define BB   4
#define SS   2048
#define SKK  2048
#define HH   512
#define NHH  8
#define DSS  64
#define MTOT (BB*SS)            // 8192
#define BATCH_ELEMS (SS*HH)     // 1048576
#define NPART 64
#define EPSN 1e-5f
#define ATTN_SCALE 0.044194173824159216f   // 1/sqrt(512)
#define LOG2E 1.4426950408889634f

#define RS   20   // gemm smem row stride (uints) = 40 bf16 -> ldmatrix conflict-free
#define BSTU 36   // attn smem row stride (uints) = 72 bf16 -> conflict-free
#define ASTG 4    // attention pipeline stages

// ---------------- scratch (static device memory; no allocations) ----------------
__device__ __nv_bfloat16 g_Xq[MTOT*HH];    // normed Q input, bf16
__device__ __nv_bfloat16 g_Xk[MTOT*HH];    // normed K input, bf16
__device__ __nv_bfloat16 g_XoH[MTOT*HH];   // normed O1, bf16 hi
__device__ __nv_bfloat16 g_XoL[MTOT*HH];   // normed O1, bf16 lo
__device__ __nv_bfloat16 g_pQh[MTOT*HH];   // pQ * ATTN_SCALE * log2(e), [m][d]
__device__ __nv_bfloat16 g_pKh[MTOT*HH];   // [m][d]
__device__ __nv_bfloat16 g_pVh[MTOT*HH];   // [m][d]
__device__ float g_O1[MTOT*HH];
__device__ __nv_bfloat16 g_wqh[HH*HH], g_wkh[HH*HH], g_wvh[HH*HH];
__device__ __nv_bfloat16 g_wch[HH*HH], g_wcl[HH*HH];
__device__ float g_part[2][BB][NPART][2];   // Q/K input partial sums
__device__ float g_apart[BB][NHH*16][2];    // O1 partial sums (from attention blocks)

// ---------------- helpers ----------------
__device__ __forceinline__ unsigned packbf(float lo, float hi){
    unsigned r; asm("cvt.rn.bf16x2.f32 %0, %1, %2;" : "=r"(r) : "f"(hi), "f"(lo)); return r;
}
__device__ __forceinline__ float ex2f(float x){
    float y; asm("ex2.approx.ftz.f32 %0, %1;" : "=f"(y) : "f"(x)); return y;
}
__device__ __forceinline__ void mma_bf16(float c[4], const unsigned a[4], const unsigned b[2]){
    asm volatile("mma.sync.aligned.m16n8k16.row.col.f32.bf16.bf16.f32 "
        "{%0,%1,%2,%3}, {%4,%5,%6,%7}, {%8,%9}, {%0,%1,%2,%3};"
        : "+f"(c[0]), "+f"(c[1]), "+f"(c[2]), "+f"(c[3])
        : "r"(a[0]), "r"(a[1]), "r"(a[2]), "r"(a[3]), "r"(b[0]), "r"(b[1]));
}
__device__ __forceinline__ void ldm_x4(unsigned r[4], uint32_t addr){
    asm volatile("ldmatrix.sync.aligned.m8n8.x4.shared.b16 {%0,%1,%2,%3}, [%4];"
        : "=r"(r[0]), "=r"(r[1]), "=r"(r[2]), "=r"(r[3]) : "r"(addr));
}
__device__ __forceinline__ void ldm_x4_t(unsigned r[4], uint32_t addr){
    asm volatile("ldmatrix.sync.aligned.m8n8.x4.trans.shared.b16 {%0,%1,%2,%3}, [%4];"
        : "=r"(r[0]), "=r"(r[1]), "=r"(r[2]), "=r"(r[3]) : "r"(addr));
}
__device__ __forceinline__ void cp16(uint32_t dst, const void* src){
    asm volatile("cp.async.ca.shared.global [%0], [%1], 16;" :: "r"(dst), "l"(src));
}
__device__ __forceinline__ void cp_commit(){
    asm volatile("cp.async.commit_group;");
}

// ---------------- prep: convert weights to bf16 + input stats, one launch ----------------
// grid.x: [0,256) convert_w, [256,512) reduce Q slot0, [512,768) reduce K slot1
__global__ void __launch_bounds__(256) prep_kernel(
    const float* __restrict__ Q, const float* __restrict__ K,
    const float* __restrict__ wq, const float* __restrict__ wk,
    const float* __restrict__ wv, const float* __restrict__ wc)
{
    __shared__ float ss[8], sq[8];
    const int bx = blockIdx.x, t = threadIdx.x;
    if (bx < 256){
        const int i = bx * 256 + t;   // quad index < 65536
        {
            float4 v = ((const float4*)wq)[i];
            ((uint2*)(unsigned*)g_wqh)[i] = make_uint2(packbf(v.x, v.y), packbf(v.z, v.w));
        }
        {
            float4 v = ((const float4*)wk)[i];
            ((uint2*)(unsigned*)g_wkh)[i] = make_uint2(packbf(v.x, v.y), packbf(v.z, v.w));
        }
        {
            float4 v = ((const float4*)wv)[i];
            ((uint2*)(unsigned*)g_wvh)[i] = make_uint2(packbf(v.x, v.y), packbf(v.z, v.w));
        }
        {
            float4 v = ((const float4*)wc)[i];
            unsigned h0 = packbf(v.x, v.y), h1 = packbf(v.z, v.w);
            ((uint2*)(unsigned*)g_wch)[i] = make_uint2(h0, h1);
            float hx = __uint_as_float(h0 << 16), hy = __uint_as_float(h0 & 0xffff0000u);
            float hz = __uint_as_float(h1 << 16), hw = __uint_as_float(h1 & 0xffff0000u);
            ((uint2*)(unsigned*)g_wcl)[i] = make_uint2(packbf(v.x - hx, v.y - hy), packbf(v.z - hz, v.w - hw));
        }
        return;
    }
    const int slot = (bx >= 512) ? 1 : 0;
    const int idx = bx - 256 - slot*256;
    const int batch = idx >> 6, part = idx & 63;
    const float* x = slot ? K : Q;
    const float4* p = (const float4*)(x + (size_t)batch*BATCH_ELEMS + (size_t)part*(BATCH_ELEMS/NPART));
    float s = 0.f, q = 0.f;
#pragma unroll
    for (int i = 0; i < 16; i++){
        float4 v = p[t + 256*i];
        s += v.x + v.y + v.z + v.w;
        q += v.x*v.x + v.y*v.y + v.z*v.z + v.w*v.w;
    }
#pragma unroll
    for (int off = 16; off; off >>= 1){
        s += __shfl_xor_sync(0xffffffffu, s, off);
        q += __shfl_xor_sync(0xffffffffu, q, off);
    }
    const int w = t >> 5;
    if ((t & 31) == 0){ ss[w] = s; sq[w] = q; }
    __syncthreads();
    if (t == 0){
        float S_ = 0.f, Q_ = 0.f;
#pragma unroll
        for (int i = 0; i < 8; i++){ S_ += ss[i]; Q_ += sq[i]; }
        g_part[slot][batch][part][0] = S_;
        g_part[slot][batch][part][1] = Q_;
    }
}

// ---------------- norm Q/K inputs -> bf16 (stats folded in) ----------------
// grid 8192: bx<4096 -> Q slot0 -> g_Xq; else K slot1 -> g_Xk
__global__ void __launch_bounds__(256) norm_qk(
    const float* __restrict__ Q, const float* __restrict__ K,
    const float* __restrict__ gq, const float* __restrict__ bq,
    const float* __restrict__ gk, const float* __restrict__ bk)
{
    __shared__ float sred[4], smr[2];
    const int tid = threadIdx.x;
    const int slot = (blockIdx.x >= 4096) ? 1 : 0;
    const int i = (blockIdx.x - slot*4096) * 256 + tid;   // quad index < 1048576
    const int batch = i >> 18;
    if (tid < 64){
        float s = g_part[slot][batch][tid][0];
        float q = g_part[slot][batch][tid][1];
#pragma unroll
        for (int off = 16; off; off >>= 1){
            s += __shfl_xor_sync(0xffffffffu, s, off);
            q += __shfl_xor_sync(0xffffffffu, q, off);
        }
        if ((tid & 31) == 0){ sred[(tid>>5)*2] = s; sred[(tid>>5)*2+1] = q; }
    }
    __syncthreads();
    if (tid == 0){
        float S = sred[0] + sred[2], Qa = sred[1] + sred[3];
        float mean = S * (1.0f/(float)BATCH_ELEMS);
        float var  = Qa * (1.0f/(float)BATCH_ELEMS) - mean*mean;
        smr[0] = mean; smr[1] = rsqrtf(var + EPSN);
    }
    __syncthreads();
    const float mean = smr[0], rstd = smr[1];

    const float* X = slot ? K : Q;
    const float* gg = slot ? gk : gq;
    const float* bb = slot ? bk : bq;
    unsigned* outHi = slot ? (unsigned*)g_Xk : (unsigned*)g_Xq;
    const int kq = i & 127;
    const float4 x = ((const float4*)X)[i];
    const float4 g4 = ((const float4*)gg)[kq];
    const float4 b4 = ((const float4*)bb)[kq];
    float4 y;
    y.x = (x.x - mean)*rstd*g4.x + b4.x;
    y.y = (x.y - mean)*rstd*g4.y + b4.y;
    y.z = (x.z - mean)*rstd*g4.z + b4.z;
    y.w = (x.w - mean)*rstd*g4.w + b4.w;
    ((uint2*)outHi)[i] = make_uint2(packbf(y.x, y.y), packbf(y.z, y.w));
}

// ---------------- norm O1 -> bf16 hi/lo (stats from attention partials) ----------------
__global__ void __launch_bounds__(256) norm_o1(
    const float* __restrict__ O1,
    const float* __restrict__ g0, const float* __restrict__ beta0)
{
    __shared__ float sred[8], smr[2];
    const int tid = threadIdx.x;
    const int i = blockIdx.x * 256 + tid;
    const int batch = i >> 18;
    if (tid < 128){
        float s = g_apart[batch][tid][0];
        float q = g_apart[batch][tid][1];
#pragma unroll
        for (int off = 16; off; off >>= 1){
            s += __shfl_xor_sync(0xffffffffu, s, off);
            q += __shfl_xor_sync(0xffffffffu, q, off);
        }
        if ((tid & 31) == 0){ sred[(tid>>5)*2] = s; sred[(tid>>5)*2+1] = q; }
    }
    __syncthreads();
    if (tid == 0){
        float S = sred[0] + sred[2] + sred[4] + sred[6];
        float Qa = sred[1] + sred[3] + sred[5] + sred[7];
        float mean = S * (1.0f/(float)BATCH_ELEMS);
        float var  = Qa * (1.0f/(float)BATCH_ELEMS) - mean*mean;
        smr[0] = mean; smr[1] = rsqrtf(var + EPSN);
    }
    __syncthreads();
    const float mean = smr[0], rstd = smr[1];

    const int kq = i & 127;
    const float4 x = ((const float4*)O1)[i];
    const float4 g4 = ((const float4*)g0)[kq];
    const float4 b4 = ((const float4*)beta0)[kq];
    float4 y;
    y.x = (x.x - mean)*rstd*g4.x + b4.x;
    y.y = (x.y - mean)*rstd*g4.y + b4.y;
    y.z = (x.z - mean)*rstd*g4.z + b4.z;
    y.w = (x.w - mean)*rstd*g4.w + b4.w;
    unsigned h0 = packbf(y.x, y.y), h1 = packbf(y.z, y.w);
    ((uint2*)(unsigned*)g_XoH)[i] = make_uint2(h0, h1);
    float hx = __uint_as_float(h0 << 16), hy = __uint_as_float(h0 & 0xffff0000u);
    float hz = __uint_as_float(h1 << 16), hw = __uint_as_float(h1 & 0xffff0000u);
    ((uint2*)(unsigned*)g_XoL)[i] = make_uint2(packbf(y.x - hx, y.y - hy), packbf(y.z - hz, y.w - hw));
}

// ---------------- fused Q/K/V projection GEMM, 3-stage cp.async ----------------
__global__ void __launch_bounds__(256, 2) gemm_proj(
    const float* __restrict__ bq, const float* __restrict__ bk, const float* __restrict__ bv)
{
    extern __shared__ unsigned smu[];
    unsigned* As = smu;                      // [3][128][RS]
    unsigned* Ws = smu + 3*128*RS;
    const uint32_t sA = (uint32_t)__cvta_generic_to_shared(As);
    const uint32_t sW = (uint32_t)__cvta_generic_to_shared(Ws);

    const int tid  = threadIdx.x;
    const int lane = tid & 31, w = tid >> 5;
    const int g = lane >> 2, t4 = lane & 3;
    const int which = blockIdx.x >> 2;
    const __nv_bfloat16* A = (which == 0) ? g_Xq : g_Xk;
    const __nv_bfloat16* W = (which == 0) ? g_wqh : (which == 1) ? g_wkh : g_wvh;
    const float* biasp = (which == 0) ? bq : (which == 1) ? bk : bv;
    __nv_bfloat16* outp = (which == 0) ? g_pQh : (which == 1) ? g_pKh : g_pVh;
    const float scl = (which == 0) ? (ATTN_SCALE * LOG2E) : 1.0f;
    const int n0 = (blockIdx.x & 3) * 128;
    const int m0 = blockIdx.y * 128;

    const int mw = w >> 1, nw = w & 1;
    const int mrow = mw * 32, nrow = nw * 64;

    float acc[2][8][4];
#pragma unroll
    for (int i = 0; i < 2; i++)
#pragma unroll
        for (int j = 0; j < 8; j++)
#pragma unroll
            for (int r = 0; r < 4; r++) acc[i][j][r] = 0.f;

    const int aRow  = lane & 15;
    const int aColU = (lane >> 4) << 2;
    const int bRow  = ((lane >> 4) << 3) + (lane & 7);
    const int bColU = ((lane >> 3) & 1) << 2;

    auto loadTile = [&](int kt, int s){
        const int kb = kt * 32;
#pragma unroll
        for (int i = 0; i < 2; i++){
            const int c = tid + 256*i;
            const int row = c >> 2, seg = c & 3;
            cp16(sA + (uint32_t)(s*128*RS + row*RS + seg*4)*4, A + (size_t)(m0 + row)*HH + kb + seg*8);
            cp16(sW + (uint32_t)(s*128*RS + row*RS + seg*4)*4, W + (size_t)(n0 + row)*HH + kb + seg*8);
        }
    };

    loadTile(0, 0); cp_commit();
    loadTile(1, 1); cp_commit();

    for (int kt = 0; kt < 16; kt++){
        const int s = kt % 3;
        if (kt + 2 < 16) loadTile(kt + 2, (kt + 2) % 3);
        cp_commit();
        asm volatile("cp.async.wait_group 2;");
        __syncthreads();

        const uint32_t aBase = sA + (uint32_t)(s*128*RS)*4;
        const uint32_t wBase = sW + (uint32_t)(s*128*RS)*4;
#pragma unroll
        for (int ks = 0; ks < 2; ks++){
            unsigned ah[2][4];
#pragma unroll
            for (int i = 0; i < 2; i++)
                ldm_x4(ah[i], aBase + (uint32_t)((mrow + i*16 + aRow)*RS + ks*8 + aColU)*4);
            unsigned bh[4][4];
#pragma unroll
            for (int jj = 0; jj < 4; jj++)
                ldm_x4(bh[jj], wBase + (uint32_t)((nrow + jj*16 + bRow)*RS + ks*8 + bColU)*4);
#pragma unroll
            for (int i = 0; i < 2; i++)
#pragma unroll
                for (int jj = 0; jj < 4; jj++){
                    mma_bf16(acc[i][2*jj],   ah[i], bh[jj]);
                    mma_bf16(acc[i][2*jj+1], ah[i], bh[jj] + 2);
                }
        }
        __syncthreads();
    }

#pragma unroll
    for (int i = 0; i < 2; i++){
#pragma unroll
        for (int j = 0; j < 8; j++){
            const int col = n0 + nrow + j*8 + 2*t4;
            const float2 bs = *(const float2*)&biasp[col];
#pragma unroll
            for (int hh = 0; hh < 2; hh++){
                const int row = m0 + mrow + i*16 + g + 8*hh;
                float cx = acc[i][j][2*hh]   + bs.x;
                float cy = acc[i][j][2*hh+1] + bs.y;
                ((unsigned*)outp)[(size_t)row*(HH/2) + (col >> 1)] = packbf(cx*scl, cy*scl);
            }
        }
    }
}

// ---------------- final GEMM: out = res + relu(A.W^T + bias), 3-term bf16 split ----------------
// 2-stage pipeline, 2 blocks/SM -> 256 blocks fit one wave.
__global__ void __launch_bounds__(256, 2) gemm_final(
    const float* __restrict__ bc, float* __restrict__ out, const float* __restrict__ res)
{
    extern __shared__ unsigned smu[];
    const int AROWS = 256;
    unsigned* As = smu;                      // [2][256][RS]
    unsigned* Ws = smu + 2*AROWS*RS;
    const uint32_t sA = (uint32_t)__cvta_generic_to_shared(As);
    const uint32_t sW = (uint32_t)__cvta_generic_to_shared(Ws);

    const int tid  = threadIdx.x;
    const int lane = tid & 31, w = tid >> 5;
    const int g = lane >> 2, t4 = lane & 3;
    const int n0 = (int)blockIdx.x * 128;
    const int m0 = blockIdx.y * 128;

    const int mw = w >> 1, nw = w & 1;
    const int mrow = mw * 32, nrow = nw * 64;

    float acc[2][8][4];
#pragma unroll
    for (int i = 0; i < 2; i++)
#pragma unroll
        for (int j = 0; j < 8; j++)
#pragma unroll
            for (int r = 0; r < 4; r++) acc[i][j][r] = 0.f;

    const int aRow  = lane & 15;
    const int aColU = (lane >> 4) << 2;
    const int bRow  = ((lane >> 4) << 3) + (lane & 7);
    const int bColU = ((lane >> 3) & 1) << 2;

    auto loadTile = [&](int kt, int s){
        const int kb = kt * 32;
#pragma unroll
        for (int i = 0; i < 4; i++){
            const int c = tid + 256*i;
            const int row = c >> 2, seg = c & 3;
            const __nv_bfloat16* srcA = (row >= 128)
                ? (g_XoL + (size_t)(m0 + row - 128)*HH + kb + seg*8)
                : (g_XoH + (size_t)(m0 + row)*HH + kb + seg*8);
            cp16(sA + (uint32_t)(s*AROWS*RS + row*RS + seg*4)*4, srcA);
            const __nv_bfloat16* srcW = (row >= 128)
                ? (g_wcl + (size_t)(n0 + row - 128)*HH + kb + seg*8)
                : (g_wch + (size_t)(n0 + row)*HH + kb + seg*8);
            cp16(sW + (uint32_t)(s*AROWS*RS + row*RS + seg*4)*4, srcW);
        }
    };

    loadTile(0, 0); cp_commit();
    loadTile(1, 1); cp_commit();

    for (int kt = 0; kt < 16; kt++){
        const int s = kt & 1;
        if (kt + 1 < 16) asm volatile("cp.async.wait_group 1;");
        else             asm volatile("cp.async.wait_group 0;");
        __syncthreads();

        const uint32_t aBase = sA + (uint32_t)(s*AROWS*RS)*4;
        const uint32_t wBase = sW + (uint32_t)(s*AROWS*RS)*4;
#pragma unroll
        for (int ks = 0; ks < 2; ks++){
            unsigned ah[2][4], alo_[2][4];
#pragma unroll
            for (int i = 0; i < 2; i++){
                ldm_x4(ah[i],   aBase + (uint32_t)((mrow + i*16 + aRow)*RS + ks*8 + aColU)*4);
                ldm_x4(alo_[i], aBase + (uint32_t)((128 + mrow + i*16 + aRow)*RS + ks*8 + aColU)*4);
            }
            // per-jj B loading keeps live regs low (fits 128-reg cap without spill)
#pragma unroll
            for (int jj = 0; jj < 4; jj++){
                unsigned bh[4], bl[4];
                ldm_x4(bh, wBase + (uint32_t)((nrow + jj*16 + bRow)*RS + ks*8 + bColU)*4);
                ldm_x4(bl, wBase + (uint32_t)((128 + nrow + jj*16 + bRow)*RS + ks*8 + bColU)*4);
#pragma unroll
                for (int i = 0; i < 2; i++){
                    mma_bf16(acc[i][2*jj],   ah[i], bh);
                    mma_bf16(acc[i][2*jj+1], ah[i], bh + 2);
                    mma_bf16(acc[i][2*jj],   ah[i], bl);
                    mma_bf16(acc[i][2*jj+1], ah[i], bl + 2);
                    mma_bf16(acc[i][2*jj],   alo_[i], bh);
                    mma_bf16(acc[i][2*jj+1], alo_[i], bh + 2);
                }
            }
        }
        __syncthreads();   // all warps done with stage s before its refill
        if (kt + 2 < 16){ loadTile(kt + 2, s); cp_commit(); }
    }

#pragma unroll
    for (int i = 0; i < 2; i++){
#pragma unroll
        for (int j = 0; j < 8; j++){
            const int col = n0 + nrow + j*8 + 2*t4;
            const float2 bs = *(const float2*)&bc[col];
#pragma unroll
            for (int hh = 0; hh < 2; hh++){
                const int row = m0 + mrow + i*16 + g + 8*hh;
                float cx = acc[i][j][2*hh]   + bs.x;
                float cy = acc[i][j][2*hh+1] + bs.y;
                const float2 rv = *(const float2*)&res[(size_t)row*HH + col];
                float2 o;
                o.x = rv.x + fmaxf(cx, 0.f);
                o.y = rv.y + fmaxf(cy, 0.f);
                *(float2*)&out[(size_t)row*HH + col] = o;
            }
        }
    }
}

// ---------------- flash attention: R9 structure (two-phase tiles) + deferred l ----------------
// No-max softmax (P = 2^s). l partials accumulate per-thread; quad-shuffled once at the end.
// 128-thr blocks, 2 blocks/SM; warp owns 32 q-rows x 64 keys; 4-stage cp.async,
// 1 sync per 2 key-tiles.
__global__ void __launch_bounds__(128, 2) attn_mma(
    const float* __restrict__ Qraw, float* __restrict__ O1)
{
    extern __shared__ unsigned smu[];
    unsigned* KsBase = smu;                  // [ASTG][64][BSTU]
    unsigned* VsBase = smu + ASTG*64*BSTU;   // [ASTG][64][BSTU]
    unsigned* Qs     = smu;                  // staging alias (dead after frag extraction)
    __shared__ float sb[4][2];

    const int tid  = threadIdx.x;
    const int lane = tid & 31, w = tid >> 5;   // w in 0..3
    const int g = lane >> 2, t4 = lane & 3;

    const int qt = blockIdx.x, h = blockIdx.y, b = blockIdx.z;
    const int hoff = h * DSS;
    const int qrow0 = b * SS + qt * 128;

    const uint32_t smemK = (uint32_t)__cvta_generic_to_shared(KsBase);
    const uint32_t smemV = (uint32_t)__cvta_generic_to_shared(VsBase);
    const uint32_t smemQ = (uint32_t)__cvta_generic_to_shared(Qs);

    // ---- stage Q tile (cp.async), extract both 16-row A-frag groups
    {
#pragma unroll
        for (int i = 0; i < 8; i++){
            const int ch = tid + 128*i;          // 1024 chunks: 128 rows x 8 segs
            const int row = ch >> 3, c = ch & 7;
            cp16(smemQ + (uint32_t)(row*BSTU + c*4)*4, g_pQh + (size_t)(qrow0 + row)*HH + hoff + c*8);
        }
        cp_commit();
        asm volatile("cp.async.wait_group 0;");
    }
    __syncthreads();

    unsigned q[2][4][4];
    {
        const int aRow = lane & 15, aColU = (lane >> 4) << 2;
#pragma unroll
        for (int hh = 0; hh < 2; hh++)
#pragma unroll
            for (int kc = 0; kc < 4; kc++)
                ldm_x4(q[hh][kc], smemQ + (uint32_t)((w*32 + hh*16 + aRow)*BSTU + kc*8 + aColU)*4);
    }
    __syncthreads();   // Qs dead; K/V pipeline reuses the memory

    float o[2][8][4];
#pragma unroll
    for (int hh = 0; hh < 2; hh++)
#pragma unroll
        for (int j = 0; j < 8; j++)
#pragma unroll
            for (int r = 0; r < 4; r++) o[hh][j][r] = 0.f;
    float lv[4];   // per-thread partial row sums (quad-reduced in epilogue)
#pragma unroll
    for (int r = 0; r < 4; r++) lv[r] = 0.f;

    const __nv_bfloat16* gK0 = g_pKh + ((size_t)b * SKK) * HH + hoff;
    const __nv_bfloat16* gV0 = g_pVh + ((size_t)b * SKK) * HH + hoff;

    auto loadKV = [&](int t, int s){
        const __nv_bfloat16* gK = gK0 + (size_t)t*64*HH;
        const __nv_bfloat16* gV = gV0 + (size_t)t*64*HH;
#pragma unroll
        for (int i = 0; i < 4; i++){
            const int ch = tid + 128*i;          // 512 chunks: 64 rows x 8 segs
            const int row = ch >> 3, c = ch & 7;
            cp16(smemK + (uint32_t)(s*64*BSTU + row*BSTU + c*4)*4, gK + (size_t)row*HH + c*8);
            cp16(smemV + (uint32_t)(s*64*BSTU + row*BSTU + c*4)*4, gV + (size_t)row*HH + c*8);
        }
    };

    loadKV(0, 0); cp_commit();
    loadKV(1, 1); cp_commit();

    const int kRow  = lane & 7;
    const int kColU = (lane >> 3) << 2;
    const int vRow  = lane & 15;
    const int vColU = (lane >> 4) << 2;

    for (int tt = 0; tt < SKK/64; tt += 2){
        // tiles tt, tt+1 are the only pending groups -> drain, then one barrier
        asm volatile("cp.async.wait_group 0;");
        __syncthreads();   // also protects stages (tt+2)&3, (tt+3)&3 (consumed last iter)
        if (tt + 2 < SKK/64){ loadKV(tt + 2, (tt + 2) & (ASTG-1)); cp_commit(); }
        if (tt + 3 < SKK/64){ loadKV(tt + 3, (tt + 3) & (ASTG-1)); cp_commit(); }

#pragma unroll
        for (int u = 0; u < 2; u++){
            const int s = (tt + u) & (ASTG-1);
            const uint32_t kBase = smemK + (uint32_t)(s*64*BSTU)*4;
            const uint32_t vBase = smemV + (uint32_t)(s*64*BSTU)*4;

            // ---- S = Q K^T for both 16-row halves (K frags loaded once)
            float sacc[2][8][4];
#pragma unroll
            for (int hh = 0; hh < 2; hh++)
#pragma unroll
                for (int j = 0; j < 8; j++)
#pragma unroll
                    for (int r = 0; r < 4; r++) sacc[hh][j][r] = 0.f;

#pragma unroll
            for (int j = 0; j < 8; j++){
                unsigned kb0[4], kb1[4];
                ldm_x4(kb0, kBase + (uint32_t)((j*8 + kRow)*BSTU + kColU)*4);
                ldm_x4(kb1, kBase + (uint32_t)((j*8 + kRow)*BSTU + 16 + kColU)*4);
#pragma unroll
                for (int hh = 0; hh < 2; hh++){
                    mma_bf16(sacc[hh][j], q[hh][0], kb0);
                    mma_bf16(sacc[hh][j], q[hh][1], kb0 + 2);
                    mma_bf16(sacc[hh][j], q[hh][2], kb1);
                    mma_bf16(sacc[hh][j], q[hh][3], kb1 + 2);
                }
            }

            // ---- P = 2^s (no max); per-thread l partials only (no shuffles here)
#pragma unroll
            for (int hh = 0; hh < 2; hh++){
                float rs0 = 0.f, rs1 = 0.f;
#pragma unroll
                for (int j = 0; j < 8; j++){
                    sacc[hh][j][0] = ex2f(sacc[hh][j][0]);
                    sacc[hh][j][1] = ex2f(sacc[hh][j][1]);
                    sacc[hh][j][2] = ex2f(sacc[hh][j][2]);
                    sacc[hh][j][3] = ex2f(sacc[hh][j][3]);
                    rs0 += sacc[hh][j][0] + sacc[hh][j][1];
                    rs1 += sacc[hh][j][2] + sacc[hh][j][3];
                }
                lv[hh*2]   += rs0;
                lv[hh*2+1] += rs1;
            }

            // ---- O += P V (V frags loaded once per kg/jp, used by both halves)
#pragma unroll
            for (int kg = 0; kg < 4; kg++){
                unsigned pa[2][4];
#pragma unroll
                for (int hh = 0; hh < 2; hh++){
                    pa[hh][0] = packbf(sacc[hh][2*kg  ][0], sacc[hh][2*kg  ][1]);
                    pa[hh][1] = packbf(sacc[hh][2*kg  ][2], sacc[hh][2*kg  ][3]);
                    pa[hh][2] = packbf(sacc[hh][2*kg+1][0], sacc[hh][2*kg+1][1]);
                    pa[hh][3] = packbf(sacc[hh][2*kg+1][2], sacc[hh][2*kg+1][3]);
                }
#pragma unroll
                for (int jp = 0; jp < 4; jp++){
                    unsigned vb[4];
                    ldm_x4_t(vb, vBase + (uint32_t)((kg*16 + vRow)*BSTU + jp*8 + vColU)*4);
#pragma unroll
                    for (int hh = 0; hh < 2; hh++){
                        mma_bf16(o[hh][2*jp],   pa[hh], vb);
                        mma_bf16(o[hh][2*jp+1], pa[hh], vb + 2);
                    }
                }
            }
        }
    }

    // ---- deferred l reduction (quad lanes hold disjoint column partials)
#pragma unroll
    for (int r = 0; r < 4; r++){
        lv[r] += __shfl_xor_sync(0xffffffffu, lv[r], 1);
        lv[r] += __shfl_xor_sync(0xffffffffu, lv[r], 2);
    }

    // ---- epilogue: O1 = Qraw + O / l, with fused sum/sumsq for set-norm stats
    float s1 = 0.f, s2 = 0.f;
#pragma unroll
    for (int hh = 0; hh < 2; hh++){
        const float inv0 = 1.0f / lv[hh*2], inv1 = 1.0f / lv[hh*2+1];
        const int row0 = qrow0 + w*32 + hh*16 + g;
#pragma unroll
        for (int jd = 0; jd < 8; jd++){
            const int col = hoff + jd*8 + 2*t4;
            {
                const float2 qv = *(const float2*)&Qraw[(size_t)row0*HH + col];
                float2 ov; ov.x = qv.x + o[hh][jd][0]*inv0; ov.y = qv.y + o[hh][jd][1]*inv0;
                *(float2*)&O1[(size_t)row0*HH + col] = ov;
                s1 += ov.x + ov.y; s2 += ov.x*ov.x + ov.y*ov.y;
            }
            {
                const float2 qv = *(const float2*)&Qraw[(size_t)(row0+8)*HH + col];
                float2 ov; ov.x = qv.x + o[hh][jd][2]*inv1; ov.y = qv.y + o[hh][jd][3]*inv1;
                *(float2*)&O1[(size_t)(row0+8)*HH + col] = ov;
                s1 += ov.x + ov.y; s2 += ov.x*ov.x + ov.y*ov.y;
            }
        }
    }
#pragma unroll
    for (int off = 16; off; off >>= 1){
        s1 += __shfl_xor_sync(0xffffffffu, s1, off);
        s2 += __shfl_xor_sync(0xffffffffu, s2, off);
    }
    if (lane == 0){ sb[w][0] = s1; sb[w][1] = s2; }
    __syncthreads();
    if (tid == 0){
        float a = 0.f, c = 0.f;
#pragma unroll
        for (int i = 0; i < 4; i++){ a += sb[i][0]; c += sb[i][1]; }
        g_apart[b][h*16 + qt][0] = a;
        g_apart[b][h*16 + qt][1] = c;
    }
}

// ---------------- launcher ----------------
extern "C" void kernel_launch(void* const* d_in, const int* in_sizes, int n_in,
                              void* d_out, int out_size)
{
    (void)in_sizes; (void)n_in; (void)out_size;
    const float* Q     = (const float*)d_in[0];
    const float* K     = (const float*)d_in[1];
    const float* wq    = (const float*)d_in[2];
    const float* bq    = (const float*)d_in[3];
    const float* wk    = (const float*)d_in[4];
    const float* bk    = (const float*)d_in[5];
    const float* wv    = (const float*)d_in[6];
    const float* bv    = (const float*)d_in[7];
    const float* wc    = (const float*)d_in[8];
    const float* bc    = (const float*)d_in[9];
    const float* gq    = (const float*)d_in[10];
    const float* betaq = (const float*)d_in[11];
    const float* gk    = (const float*)d_in[12];
    const float* betak = (const float*)d_in[13];
    const float* g0    = (const float*)d_in[14];
    const float* beta0 = (const float*)d_in[15];
    float* out = (float*)d_out;

    float* O1p;
    cudaGetSymbolAddress((void**)&O1p, g_O1);

    const int PROJ_SMEM = 3 * 2 * 128 * RS * 4;      // 61440
    const int FIN_SMEM  = 2 * 2 * 256 * RS * 4;      // 81920
    const int ATTN_SMEM = 2 * ASTG * 64 * BSTU * 4;  // 73728

    cudaFuncSetAttribute(gemm_proj,  cudaFuncAttributeMaxDynamicSharedMemorySize, PROJ_SMEM);
    cudaFuncSetAttribute(gemm_final, cudaFuncAttributeMaxDynamicSharedMemorySize, FIN_SMEM);
    cudaFuncSetAttribute(attn_mma,   cudaFuncAttributeMaxDynamicSharedMemorySize, ATTN_SMEM);

    // 1. weights->bf16 + Q/K input stats
    prep_kernel<<<768, 256>>>(Q, K, wq, wk, wv, wc);
    // 2. normed inputs -> bf16 (stats folded in)
    norm_qk<<<8192, 256>>>(Q, K, gq, betaq, gk, betak);
    // 3. Q/K/V projections, one launch
    gemm_proj<<<dim3(12, 64), 256, PROJ_SMEM>>>(bq, bk, bv);
    // 4. attention + residual + fused O1 stats
    attn_mma<<<dim3(SS/128, NHH, BB), 128, ATTN_SMEM>>>(Q, O1p);
    // 5. norm O1 -> bf16 hi/lo (stats from attention partials)
    norm_o1<<<4096, 256>>>(O1p, g0, beta0);
    // 6. out = O1 + relu(norm(O1) @ wc^T + bc)
    gemm_final<<<dim3(4, 64), 256, FIN_SMEM>>>(bc, out, O1p);
}

// round 12
// speedup vs baseline: 1.1216x; 1.0164x over previous
#include <cuda_runtime.h>
#include <cuda_bf16.h>
#include <cstdint>

#define BB   4
#define SS   2048
#define SKK  2048
#define HH   512
#define NHH  8
#define DSS  64
#define MTOT (BB*SS)            // 8192
#define BATCH_ELEMS (SS*HH)     // 1048576
#define NPART 64
#define EPSN 1e-5f
#define ATTN_SCALE 0.044194173824159216f   // 1/sqrt(512)
#define LOG2E 1.4426950408889634f

#define RS   20   // gemm smem row stride (uints) = 40 bf16 -> ldmatrix conflict-free
#define BSTU 36   // attn smem row stride (uints) = 72 bf16 -> conflict-free
#define ASTG 4    // attention pipeline stages

// ---------------- scratch (static device memory; no allocations) ----------------
__device__ __nv_bfloat16 g_Xq[MTOT*HH];    // normed Q input, bf16
__device__ __nv_bfloat16 g_Xk[MTOT*HH];    // normed K input, bf16
__device__ __nv_bfloat16 g_XoH[MTOT*HH];   // normed O1, bf16 hi
__device__ __nv_bfloat16 g_XoL[MTOT*HH];   // normed O1, bf16 lo
__device__ __nv_bfloat16 g_pQh[MTOT*HH];   // pQ * ATTN_SCALE * log2(e), [m][d]
__device__ __nv_bfloat16 g_pKh[MTOT*HH];   // [m][d]
__device__ __nv_bfloat16 g_pVh[MTOT*HH];   // [m][d]
__device__ float g_O1[MTOT*HH];
__device__ __nv_bfloat16 g_wqh[HH*HH], g_wkh[HH*HH], g_wvh[HH*HH];
__device__ __nv_bfloat16 g_wch[HH*HH], g_wcl[HH*HH];
__device__ float g_part[2][BB][NPART][2];   // Q/K input partial sums
__device__ float g_apart[BB][NHH*16][2];    // O1 partial sums (from attention blocks)

// ---------------- helpers ----------------
__device__ __forceinline__ unsigned packbf(float lo, float hi){
    unsigned r; asm("cvt.rn.bf16x2.f32 %0, %1, %2;" : "=r"(r) : "f"(hi), "f"(lo)); return r;
}
__device__ __forceinline__ float ex2f(float x){
    float y; asm("ex2.approx.ftz.f32 %0, %1;" : "=f"(y) : "f"(x)); return y;
}
__device__ __forceinline__ void mma_bf16(float c[4], const unsigned a[4], const unsigned b[2]){
    asm volatile("mma.sync.aligned.m16n8k16.row.col.f32.bf16.bf16.f32 "
        "{%0,%1,%2,%3}, {%4,%5,%6,%7}, {%8,%9}, {%0,%1,%2,%3};"
        : "+f"(c[0]), "+f"(c[1]), "+f"(c[2]), "+f"(c[3])
        : "r"(a[0]), "r"(a[1]), "r"(a[2]), "r"(a[3]), "r"(b[0]), "r"(b[1]));
}
__device__ __forceinline__ void ldm_x4(unsigned r[4], uint32_t addr){
    asm volatile("ldmatrix.sync.aligned.m8n8.x4.shared.b16 {%0,%1,%2,%3}, [%4];"
        : "=r"(r[0]), "=r"(r[1]), "=r"(r[2]), "=r"(r[3]) : "r"(addr));
}
__device__ __forceinline__ void ldm_x4_t(unsigned r[4], uint32_t addr){
    asm volatile("ldmatrix.sync.aligned.m8n8.x4.trans.shared.b16 {%0,%1,%2,%3}, [%4];"
        : "=r"(r[0]), "=r"(r[1]), "=r"(r[2]), "=r"(r[3]) : "r"(addr));
}
__device__ __forceinline__ void cp16(uint32_t dst, const void* src){
    asm volatile("cp.async.ca.shared.global [%0], [%1], 16;" :: "r"(dst), "l"(src));
}
__device__ __forceinline__ void cp_commit(){
    asm volatile("cp.async.commit_group;");
}

// ---------------- prep: convert weights to bf16 + input stats, one launch ----------------
// grid.x: [0,256) convert_w, [256,512) reduce Q slot0, [512,768) reduce K slot1
__global__ void __launch_bounds__(256) prep_kernel(
    const float* __restrict__ Q, const float* __restrict__ K,
    const float* __restrict__ wq, const float* __restrict__ wk,
    const float* __restrict__ wv, const float* __restrict__ wc)
{
    __shared__ float ss[8], sq[8];
    const int bx = blockIdx.x, t = threadIdx.x;
    if (bx < 256){
        const int i = bx * 256 + t;   // quad index < 65536
        {
            float4 v = ((const float4*)wq)[i];
            ((uint2*)(unsigned*)g_wqh)[i] = make_uint2(packbf(v.x, v.y), packbf(v.z, v.w));
        }
        {
            float4 v = ((const float4*)wk)[i];
            ((uint2*)(unsigned*)g_wkh)[i] = make_uint2(packbf(v.x, v.y), packbf(v.z, v.w));
        }
        {
            float4 v = ((const float4*)wv)[i];
            ((uint2*)(unsigned*)g_wvh)[i] = make_uint2(packbf(v.x, v.y), packbf(v.z, v.w));
        }
        {
            float4 v = ((const float4*)wc)[i];
            unsigned h0 = packbf(v.x, v.y), h1 = packbf(v.z, v.w);
            ((uint2*)(unsigned*)g_wch)[i] = make_uint2(h0, h1);
            float hx = __uint_as_float(h0 << 16), hy = __uint_as_float(h0 & 0xffff0000u);
            float hz = __uint_as_float(h1 << 16), hw = __uint_as_float(h1 & 0xffff0000u);
            ((uint2*)(unsigned*)g_wcl)[i] = make_uint2(packbf(v.x - hx, v.y - hy), packbf(v.z - hz, v.w - hw));
        }
        return;
    }
    const int slot = (bx >= 512) ? 1 : 0;
    const int idx = bx - 256 - slot*256;
    const int batch = idx >> 6, part = idx & 63;
    const float* x = slot ? K : Q;
    const float4* p = (const float4*)(x + (size_t)batch*BATCH_ELEMS + (size_t)part*(BATCH_ELEMS/NPART));
    float s = 0.f, q = 0.f;
#pragma unroll
    for (int i = 0; i < 16; i++){
        float4 v = p[t + 256*i];
        s += v.x + v.y + v.z + v.w;
        q += v.x*v.x + v.y*v.y + v.z*v.z + v.w*v.w;
    }
#pragma unroll
    for (int off = 16; off; off >>= 1){
        s += __shfl_xor_sync(0xffffffffu, s, off);
        q += __shfl_xor_sync(0xffffffffu, q, off);
    }
    const int w = t >> 5;
    if ((t & 31) == 0){ ss[w] = s; sq[w] = q; }
    __syncthreads();
    if (t == 0){
        float S_ = 0.f, Q_ = 0.f;
#pragma unroll
        for (int i = 0; i < 8; i++){ S_ += ss[i]; Q_ += sq[i]; }
        g_part[slot][batch][part][0] = S_;
        g_part[slot][batch][part][1] = Q_;
    }
}

// ---------------- norm Q/K inputs -> bf16 (stats folded in), 4 float4/thread ----------------
// grid 2048: bx<1024 -> Q slot0 -> g_Xq; else K slot1 -> g_Xk. Block spans 1024 quads (one batch).
__global__ void __launch_bounds__(256) norm_qk(
    const float* __restrict__ Q, const float* __restrict__ K,
    const float* __restrict__ gq, const float* __restrict__ bq,
    const float* __restrict__ gk, const float* __restrict__ bk)
{
    __shared__ float sred[4], smr[2];
    const int tid = threadIdx.x;
    const int slot = (blockIdx.x >= 1024) ? 1 : 0;
    const int base = (blockIdx.x - slot*1024) * 1024 + tid;   // quad index
    const int batch = base >> 18;
    if (tid < 64){
        float s = g_part[slot][batch][tid][0];
        float q = g_part[slot][batch][tid][1];
#pragma unroll
        for (int off = 16; off; off >>= 1){
            s += __shfl_xor_sync(0xffffffffu, s, off);
            q += __shfl_xor_sync(0xffffffffu, q, off);
        }
        if ((tid & 31) == 0){ sred[(tid>>5)*2] = s; sred[(tid>>5)*2+1] = q; }
    }
    __syncthreads();
    if (tid == 0){
        float S = sred[0] + sred[2], Qa = sred[1] + sred[3];
        float mean = S * (1.0f/(float)BATCH_ELEMS);
        float var  = Qa * (1.0f/(float)BATCH_ELEMS) - mean*mean;
        smr[0] = mean; smr[1] = rsqrtf(var + EPSN);
    }
    __syncthreads();
    const float mean = smr[0], rstd = smr[1];

    const float* X = slot ? K : Q;
    const float* gg = slot ? gk : gq;
    const float* bb = slot ? bk : bq;
    unsigned* outHi = slot ? (unsigned*)g_Xk : (unsigned*)g_Xq;
#pragma unroll
    for (int it = 0; it < 4; it++){
        const int i = base + 256*it;
        const int kq = i & 127;
        const float4 x = ((const float4*)X)[i];
        const float4 g4 = ((const float4*)gg)[kq];
        const float4 b4 = ((const float4*)bb)[kq];
        float4 y;
        y.x = (x.x - mean)*rstd*g4.x + b4.x;
        y.y = (x.y - mean)*rstd*g4.y + b4.y;
        y.z = (x.z - mean)*rstd*g4.z + b4.z;
        y.w = (x.w - mean)*rstd*g4.w + b4.w;
        ((uint2*)outHi)[i] = make_uint2(packbf(y.x, y.y), packbf(y.z, y.w));
    }
}

// ---------------- norm O1 -> bf16 hi/lo (stats from attention partials), 4 float4/thread ----------------
__global__ void __launch_bounds__(256) norm_o1(
    const float* __restrict__ O1,
    const float* __restrict__ g0, const float* __restrict__ beta0)
{
    __shared__ float sred[8], smr[2];
    const int tid = threadIdx.x;
    const int base = blockIdx.x * 1024 + tid;
    const int batch = base >> 18;
    if (tid < 128){
        float s = g_apart[batch][tid][0];
        float q = g_apart[batch][tid][1];
#pragma unroll
        for (int off = 16; off; off >>= 1){
            s += __shfl_xor_sync(0xffffffffu, s, off);
            q += __shfl_xor_sync(0xffffffffu, q, off);
        }
        if ((tid & 31) == 0){ sred[(tid>>5)*2] = s; sred[(tid>>5)*2+1] = q; }
    }
    __syncthreads();
    if (tid == 0){
        float S = sred[0] + sred[2] + sred[4] + sred[6];
        float Qa = sred[1] + sred[3] + sred[5] + sred[7];
        float mean = S * (1.0f/(float)BATCH_ELEMS);
        float var  = Qa * (1.0f/(float)BATCH_ELEMS) - mean*mean;
        smr[0] = mean; smr[1] = rsqrtf(var + EPSN);
    }
    __syncthreads();
    const float mean = smr[0], rstd = smr[1];

#pragma unroll
    for (int it = 0; it < 4; it++){
        const int i = base + 256*it;
        const int kq = i & 127;
        const float4 x = ((const float4*)O1)[i];
        const float4 g4 = ((const float4*)g0)[kq];
        const float4 b4 = ((const float4*)beta0)[kq];
        float4 y;
        y.x = (x.x - mean)*rstd*g4.x + b4.x;
        y.y = (x.y - mean)*rstd*g4.y + b4.y;
        y.z = (x.z - mean)*rstd*g4.z + b4.z;
        y.w = (x.w - mean)*rstd*g4.w + b4.w;
        unsigned h0 = packbf(y.x, y.y), h1 = packbf(y.z, y.w);
        ((uint2*)(unsigned*)g_XoH)[i] = make_uint2(h0, h1);
        float hx = __uint_as_float(h0 << 16), hy = __uint_as_float(h0 & 0xffff0000u);
        float hz = __uint_as_float(h1 << 16), hw = __uint_as_float(h1 & 0xffff0000u);
        ((uint2*)(unsigned*)g_XoL)[i] = make_uint2(packbf(y.x - hx, y.y - hy), packbf(y.z - hz, y.w - hw));
    }
}

// ---------------- fused Q/K/V projection GEMM, 3-stage cp.async ----------------
__global__ void __launch_bounds__(256, 2) gemm_proj(
    const float* __restrict__ bq, const float* __restrict__ bk, const float* __restrict__ bv)
{
    extern __shared__ unsigned smu[];
    unsigned* As = smu;                      // [3][128][RS]
    unsigned* Ws = smu + 3*128*RS;
    const uint32_t sA = (uint32_t)__cvta_generic_to_shared(As);
    const uint32_t sW = (uint32_t)__cvta_generic_to_shared(Ws);

    const int tid  = threadIdx.x;
    const int lane = tid & 31, w = tid >> 5;
    const int g = lane >> 2, t4 = lane & 3;
    const int which = blockIdx.x >> 2;
    const __nv_bfloat16* A = (which == 0) ? g_Xq : g_Xk;
    const __nv_bfloat16* W = (which == 0) ? g_wqh : (which == 1) ? g_wkh : g_wvh;
    const float* biasp = (which == 0) ? bq : (which == 1) ? bk : bv;
    __nv_bfloat16* outp = (which == 0) ? g_pQh : (which == 1) ? g_pKh : g_pVh;
    const float scl = (which == 0) ? (ATTN_SCALE * LOG2E) : 1.0f;
    const int n0 = (blockIdx.x & 3) * 128;
    const int m0 = blockIdx.y * 128;

    const int mw = w >> 1, nw = w & 1;
    const int mrow = mw * 32, nrow = nw * 64;

    float acc[2][8][4];
#pragma unroll
    for (int i = 0; i < 2; i++)
#pragma unroll
        for (int j = 0; j < 8; j++)
#pragma unroll
            for (int r = 0; r < 4; r++) acc[i][j][r] = 0.f;

    const int aRow  = lane & 15;
    const int aColU = (lane >> 4) << 2;
    const int bRow  = ((lane >> 4) << 3) + (lane & 7);
    const int bColU = ((lane >> 3) & 1) << 2;

    auto loadTile = [&](int kt, int s){
        const int kb = kt * 32;
#pragma unroll
        for (int i = 0; i < 2; i++){
            const int c = tid + 256*i;
            const int row = c >> 2, seg = c & 3;
            cp16(sA + (uint32_t)(s*128*RS + row*RS + seg*4)*4, A + (size_t)(m0 + row)*HH + kb + seg*8);
            cp16(sW + (uint32_t)(s*128*RS + row*RS + seg*4)*4, W + (size_t)(n0 + row)*HH + kb + seg*8);
        }
    };

    loadTile(0, 0); cp_commit();
    loadTile(1, 1); cp_commit();

    for (int kt = 0; kt < 16; kt++){
        const int s = kt % 3;
        if (kt + 2 < 16) loadTile(kt + 2, (kt + 2) % 3);
        cp_commit();
        asm volatile("cp.async.wait_group 2;");
        __syncthreads();

        const uint32_t aBase = sA + (uint32_t)(s*128*RS)*4;
        const uint32_t wBase = sW + (uint32_t)(s*128*RS)*4;
#pragma unroll
        for (int ks = 0; ks < 2; ks++){
            unsigned ah[2][4];
#pragma unroll
            for (int i = 0; i < 2; i++)
                ldm_x4(ah[i], aBase + (uint32_t)((mrow + i*16 + aRow)*RS + ks*8 + aColU)*4);
            unsigned bh[4][4];
#pragma unroll
            for (int jj = 0; jj < 4; jj++)
                ldm_x4(bh[jj], wBase + (uint32_t)((nrow + jj*16 + bRow)*RS + ks*8 + bColU)*4);
#pragma unroll
            for (int i = 0; i < 2; i++)
#pragma unroll
                for (int jj = 0; jj < 4; jj++){
                    mma_bf16(acc[i][2*jj],   ah[i], bh[jj]);
                    mma_bf16(acc[i][2*jj+1], ah[i], bh[jj] + 2);
                }
        }
        __syncthreads();
    }

#pragma unroll
    for (int i = 0; i < 2; i++){
#pragma unroll
        for (int j = 0; j < 8; j++){
            const int col = n0 + nrow + j*8 + 2*t4;
            const float2 bs = *(const float2*)&biasp[col];
#pragma unroll
            for (int hh = 0; hh < 2; hh++){
                const int row = m0 + mrow + i*16 + g + 8*hh;
                float cx = acc[i][j][2*hh]   + bs.x;
                float cy = acc[i][j][2*hh+1] + bs.y;
                ((unsigned*)outp)[(size_t)row*(HH/2) + (col >> 1)] = packbf(cx*scl, cy*scl);
            }
        }
    }
}

// ---------------- final GEMM: out = res + relu(A.W^T + bias), 3-term bf16 split ----------------
// 2-stage pipeline, 2 blocks/SM -> 256 blocks fit one wave.
__global__ void __launch_bounds__(256, 2) gemm_final(
    const float* __restrict__ bc, float* __restrict__ out, const float* __restrict__ res)
{
    extern __shared__ unsigned smu[];
    const int AROWS = 256;
    unsigned* As = smu;                      // [2][256][RS]
    unsigned* Ws = smu + 2*AROWS*RS;
    const uint32_t sA = (uint32_t)__cvta_generic_to_shared(As);
    const uint32_t sW = (uint32_t)__cvta_generic_to_shared(Ws);

    const int tid  = threadIdx.x;
    const int lane = tid & 31, w = tid >> 5;
    const int g = lane >> 2, t4 = lane & 3;
    const int n0 = (int)blockIdx.x * 128;
    const int m0 = blockIdx.y * 128;

    const int mw = w >> 1, nw = w & 1;
    const int mrow = mw * 32, nrow = nw * 64;

    float acc[2][8][4];
#pragma unroll
    for (int i = 0; i < 2; i++)
#pragma unroll
        for (int j = 0; j < 8; j++)
#pragma unroll
            for (int r = 0; r < 4; r++) acc[i][j][r] = 0.f;

    const int aRow  = lane & 15;
    const int aColU = (lane >> 4) << 2;
    const int bRow  = ((lane >> 4) << 3) + (lane & 7);
    const int bColU = ((lane >> 3) & 1) << 2;

    auto loadTile = [&](int kt, int s){
        const int kb = kt * 32;
#pragma unroll
        for (int i = 0; i < 4; i++){
            const int c = tid + 256*i;
            const int row = c >> 2, seg = c & 3;
            const __nv_bfloat16* srcA = (row >= 128)
                ? (g_XoL + (size_t)(m0 + row - 128)*HH + kb + seg*8)
                : (g_XoH + (size_t)(m0 + row)*HH + kb + seg*8);
            cp16(sA + (uint32_t)(s*AROWS*RS + row*RS + seg*4)*4, srcA);
            const __nv_bfloat16* srcW = (row >= 128)
                ? (g_wcl + (size_t)(n0 + row - 128)*HH + kb + seg*8)
                : (g_wch + (size_t)(n0 + row)*HH + kb + seg*8);
            cp16(sW + (uint32_t)(s*AROWS*RS + row*RS + seg*4)*4, srcW);
        }
    };

    loadTile(0, 0); cp_commit();
    loadTile(1, 1); cp_commit();

    for (int kt = 0; kt < 16; kt++){
        const int s = kt & 1;
        if (kt + 1 < 16) asm volatile("cp.async.wait_group 1;");
        else             asm volatile("cp.async.wait_group 0;");
        __syncthreads();

        const uint32_t aBase = sA + (uint32_t)(s*AROWS*RS)*4;
        const uint32_t wBase = sW + (uint32_t)(s*AROWS*RS)*4;
#pragma unroll
        for (int ks = 0; ks < 2; ks++){
            unsigned ah[2][4], alo_[2][4];
#pragma unroll
            for (int i = 0; i < 2; i++){
                ldm_x4(ah[i],   aBase + (uint32_t)((mrow + i*16 + aRow)*RS + ks*8 + aColU)*4);
                ldm_x4(alo_[i], aBase + (uint32_t)((128 + mrow + i*16 + aRow)*RS + ks*8 + aColU)*4);
            }
            // per-jj B loading keeps live regs low (fits 128-reg cap without spill)
#pragma unroll
            for (int jj = 0; jj < 4; jj++){
                unsigned bh[4], bl[4];
                ldm_x4(bh, wBase + (uint32_t)((nrow + jj*16 + bRow)*RS + ks*8 + bColU)*4);
                ldm_x4(bl, wBase + (uint32_t)((128 + nrow + jj*16 + bRow)*RS + ks*8 + bColU)*4);
#pragma unroll
                for (int i = 0; i < 2; i++){
                    mma_bf16(acc[i][2*jj],   ah[i], bh);
                    mma_bf16(acc[i][2*jj+1], ah[i], bh + 2);
                    mma_bf16(acc[i][2*jj],   ah[i], bl);
                    mma_bf16(acc[i][2*jj+1], ah[i], bl + 2);
                    mma_bf16(acc[i][2*jj],   alo_[i], bh);
                    mma_bf16(acc[i][2*jj+1], alo_[i], bh + 2);
                }
            }
        }
        __syncthreads();   // all warps done with stage s before its refill
        if (kt + 2 < 16){ loadTile(kt + 2, s); cp_commit(); }
    }

#pragma unroll
    for (int i = 0; i < 2; i++){
#pragma unroll
        for (int j = 0; j < 8; j++){
            const int col = n0 + nrow + j*8 + 2*t4;
            const float2 bs = *(const float2*)&bc[col];
#pragma unroll
            for (int hh = 0; hh < 2; hh++){
                const int row = m0 + mrow + i*16 + g + 8*hh;
                float cx = acc[i][j][2*hh]   + bs.x;
                float cy = acc[i][j][2*hh+1] + bs.y;
                const float2 rv = *(const float2*)&res[(size_t)row*HH + col];
                float2 o;
                o.x = rv.x + fmaxf(cx, 0.f);
                o.y = rv.y + fmaxf(cy, 0.f);
                *(float2*)&out[(size_t)row*HH + col] = o;
            }
        }
    }
}

// ---------------- flash attention: half-tile (32-key) interleaved phases ----------------
// No-max softmax (P = 2^s), deferred l. Per 32-key phase: S-MMAs(32) -> V ldm -> ex2(16)
// -> pack -> PV-MMAs(32). sacc live range = 32 regs; natural usage ~190 (no spill at 2 blk/SM).
// 128-thr blocks, 2 blocks/SM; warp owns 32 q-rows x 64 keys; 4-stage cp.async,
// 1 sync per 2 key-tiles.
__global__ void __launch_bounds__(128, 2) attn_mma(
    const float* __restrict__ Qraw, float* __restrict__ O1)
{
    extern __shared__ unsigned smu[];
    unsigned* KsBase = smu;                  // [ASTG][64][BSTU]
    unsigned* VsBase = smu + ASTG*64*BSTU;   // [ASTG][64][BSTU]
    unsigned* Qs     = smu;                  // staging alias (dead after frag extraction)
    __shared__ float sb[4][2];

    const int tid  = threadIdx.x;
    const int lane = tid & 31, w = tid >> 5;   // w in 0..3
    const int g = lane >> 2, t4 = lane & 3;

    const int qt = blockIdx.x, h = blockIdx.y, b = blockIdx.z;
    const int hoff = h * DSS;
    const int qrow0 = b * SS + qt * 128;

    const uint32_t smemK = (uint32_t)__cvta_generic_to_shared(KsBase);
    const uint32_t smemV = (uint32_t)__cvta_generic_to_shared(VsBase);
    const uint32_t smemQ = (uint32_t)__cvta_generic_to_shared(Qs);

    // ---- stage Q tile (cp.async), extract both 16-row A-frag groups
    {
#pragma unroll
        for (int i = 0; i < 8; i++){
            const int ch = tid + 128*i;          // 1024 chunks: 128 rows x 8 segs
            const int row = ch >> 3, c = ch & 7;
            cp16(smemQ + (uint32_t)(row*BSTU + c*4)*4, g_pQh + (size_t)(qrow0 + row)*HH + hoff + c*8);
        }
        cp_commit();
        asm volatile("cp.async.wait_group 0;");
    }
    __syncthreads();

    unsigned q[2][4][4];
    {
        const int aRow = lane & 15, aColU = (lane >> 4) << 2;
#pragma unroll
        for (int hh = 0; hh < 2; hh++)
#pragma unroll
            for (int kc = 0; kc < 4; kc++)
                ldm_x4(q[hh][kc], smemQ + (uint32_t)((w*32 + hh*16 + aRow)*BSTU + kc*8 + aColU)*4);
    }
    __syncthreads();   // Qs dead; K/V pipeline reuses the memory

    float o[2][8][4];
#pragma unroll
    for (int hh = 0; hh < 2; hh++)
#pragma unroll
        for (int j = 0; j < 8; j++)
#pragma unroll
            for (int r = 0; r < 4; r++) o[hh][j][r] = 0.f;
    float lv[4];   // per-thread partial row sums (quad-reduced in epilogue)
#pragma unroll
    for (int r = 0; r < 4; r++) lv[r] = 0.f;

    const __nv_bfloat16* gK0 = g_pKh + ((size_t)b * SKK) * HH + hoff;
    const __nv_bfloat16* gV0 = g_pVh + ((size_t)b * SKK) * HH + hoff;

    auto loadKV = [&](int t, int s){
        const __nv_bfloat16* gK = gK0 + (size_t)t*64*HH;
        const __nv_bfloat16* gV = gV0 + (size_t)t*64*HH;
#pragma unroll
        for (int i = 0; i < 4; i++){
            const int ch = tid + 128*i;          // 512 chunks: 64 rows x 8 segs
            const int row = ch >> 3, c = ch & 7;
            cp16(smemK + (uint32_t)(s*64*BSTU + row*BSTU + c*4)*4, gK + (size_t)row*HH + c*8);
            cp16(smemV + (uint32_t)(s*64*BSTU + row*BSTU + c*4)*4, gV + (size_t)row*HH + c*8);
        }
    };

    loadKV(0, 0); cp_commit();
    loadKV(1, 1); cp_commit();

    const int kRow  = lane & 7;
    const int kColU = (lane >> 3) << 2;
    const int vRow  = lane & 15;
    const int vColU = (lane >> 4) << 2;

    for (int tt = 0; tt < SKK/64; tt += 2){
        // tiles tt, tt+1 are the only pending groups -> drain, then one barrier
        asm volatile("cp.async.wait_group 0;");
        __syncthreads();   // also protects stages (tt+2)&3, (tt+3)&3 (consumed last iter)
        if (tt + 2 < SKK/64){ loadKV(tt + 2, (tt + 2) & (ASTG-1)); cp_commit(); }
        if (tt + 3 < SKK/64){ loadKV(tt + 3, (tt + 3) & (ASTG-1)); cp_commit(); }

#pragma unroll
        for (int u = 0; u < 2; u++){
            const int s = (tt + u) & (ASTG-1);
            const uint32_t kBase = smemK + (uint32_t)(s*64*BSTU)*4;
            const uint32_t vBase = smemV + (uint32_t)(s*64*BSTU)*4;

            // ---- two 32-key phases per tile
#pragma unroll
            for (int kh = 0; kh < 2; kh++){
                // K fragments for j tiles kh*4 .. kh*4+3
                unsigned kb[4][4];   // [j-pair grouping: j0 lo/hi, j1 lo/hi ...]
                float sacc[2][4][4];
#pragma unroll
                for (int hh = 0; hh < 2; hh++)
#pragma unroll
                    for (int j = 0; j < 4; j++)
#pragma unroll
                        for (int r = 0; r < 4; r++) sacc[hh][j][r] = 0.f;

#pragma unroll
                for (int j = 0; j < 4; j++){
                    const int jg = kh*4 + j;
                    unsigned kb0[4], kb1[4];
                    ldm_x4(kb0, kBase + (uint32_t)((jg*8 + kRow)*BSTU + kColU)*4);
                    ldm_x4(kb1, kBase + (uint32_t)((jg*8 + kRow)*BSTU + 16 + kColU)*4);
#pragma unroll
                    for (int hh = 0; hh < 2; hh++){
                        mma_bf16(sacc[hh][j], q[hh][0], kb0);
                        mma_bf16(sacc[hh][j], q[hh][1], kb0 + 2);
                        mma_bf16(sacc[hh][j], q[hh][2], kb1);
                        mma_bf16(sacc[hh][j], q[hh][3], kb1 + 2);
                    }
                }

                // V fragments for this 32-key half (kg = kh*2, kh*2+1)
                unsigned vb[2][4][4];
#pragma unroll
                for (int kg = 0; kg < 2; kg++)
#pragma unroll
                    for (int jp = 0; jp < 4; jp++)
                        ldm_x4_t(vb[kg][jp], vBase + (uint32_t)(((kh*2+kg)*16 + vRow)*BSTU + jp*8 + vColU)*4);

                // P = 2^s, per-thread l partials, pack
                unsigned pa[2][2][4];   // [kg][hh]... layout: pa[kg][hh]
#pragma unroll
                for (int hh = 0; hh < 2; hh++){
#pragma unroll
                    for (int j = 0; j < 4; j++){
                        sacc[hh][j][0] = ex2f(sacc[hh][j][0]);
                        sacc[hh][j][1] = ex2f(sacc[hh][j][1]);
                        sacc[hh][j][2] = ex2f(sacc[hh][j][2]);
                        sacc[hh][j][3] = ex2f(sacc[hh][j][3]);
                    }
                    lv[hh*2]   += sacc[hh][0][0] + sacc[hh][0][1] + sacc[hh][1][0] + sacc[hh][1][1]
                                + sacc[hh][2][0] + sacc[hh][2][1] + sacc[hh][3][0] + sacc[hh][3][1];
                    lv[hh*2+1] += sacc[hh][0][2] + sacc[hh][0][3] + sacc[hh][1][2] + sacc[hh][1][3]
                                + sacc[hh][2][2] + sacc[hh][2][3] + sacc[hh][3][2] + sacc[hh][3][3];
#pragma unroll
                    for (int kg = 0; kg < 2; kg++){
                        pa[kg][hh][0] = packbf(sacc[hh][2*kg  ][0], sacc[hh][2*kg  ][1]);
                        pa[kg][hh][1] = packbf(sacc[hh][2*kg  ][2], sacc[hh][2*kg  ][3]);
                        pa[kg][hh][2] = packbf(sacc[hh][2*kg+1][0], sacc[hh][2*kg+1][1]);
                        pa[kg][hh][3] = packbf(sacc[hh][2*kg+1][2], sacc[hh][2*kg+1][3]);
                    }
                }

                // O += P V
#pragma unroll
                for (int kg = 0; kg < 2; kg++)
#pragma unroll
                    for (int jp = 0; jp < 4; jp++)
#pragma unroll
                        for (int hh = 0; hh < 2; hh++){
                            mma_bf16(o[hh][2*jp],   pa[kg][hh], vb[kg][jp]);
                            mma_bf16(o[hh][2*jp+1], pa[kg][hh], vb[kg][jp] + 2);
                        }
            }
        }
    }

    // ---- deferred l reduction (quad lanes hold disjoint column partials)
#pragma unroll
    for (int r = 0; r < 4; r++){
        lv[r] += __shfl_xor_sync(0xffffffffu, lv[r], 1);
        lv[r] += __shfl_xor_sync(0xffffffffu, lv[r], 2);
    }

    // ---- epilogue: O1 = Qraw + O / l, with fused sum/sumsq for set-norm stats
    float s1 = 0.f, s2 = 0.f;
#pragma unroll
    for (int hh = 0; hh < 2; hh++){
        const float inv0 = 1.0f / lv[hh*2], inv1 = 1.0f / lv[hh*2+1];
        const int row0 = qrow0 + w*32 + hh*16 + g;
#pragma unroll
        for (int jd = 0; jd < 8; jd++){
            const int col = hoff + jd*8 + 2*t4;
            {
                const float2 qv = *(const float2*)&Qraw[(size_t)row0*HH + col];
                float2 ov; ov.x = qv.x + o[hh][jd][0]*inv0; ov.y = qv.y + o[hh][jd][1]*inv0;
                *(float2*)&O1[(size_t)row0*HH + col] = ov;
                s1 += ov.x + ov.y; s2 += ov.x*ov.x + ov.y*ov.y;
            }
            {
                const float2 qv = *(const float2*)&Qraw[(size_t)(row0+8)*HH + col];
                float2 ov; ov.x = qv.x + o[hh][jd][2]*inv1; ov.y = qv.y + o[hh][jd][3]*inv1;
                *(float2*)&O1[(size_t)(row0+8)*HH + col] = ov;
                s1 += ov.x + ov.y; s2 += ov.x*ov.x + ov.y*ov.y;
            }
        }
    }
#pragma unroll
    for (int off = 16; off; off >>= 1){
        s1 += __shfl_xor_sync(0xffffffffu, s1, off);
        s2 += __shfl_xor_sync(0xffffffffu, s2, off);
    }
    if (lane == 0){ sb[w][0] = s1; sb[w][1] = s2; }
    __syncthreads();
    if (tid == 0){
        float a = 0.f, c = 0.f;
#pragma unroll
        for (int i = 0; i < 4; i++){ a += sb[i][0]; c += sb[i][1]; }
        g_apart[b][h*16 + qt][0] = a;
        g_apart[b][h*16 + qt][1] = c;
    }
}

// ---------------- launcher ----------------
extern "C" void kernel_launch(void* const* d_in, const int* in_sizes, int n_in,
                              void* d_out, int out_size)
{
    (void)in_sizes; (void)n_in; (void)out_size;
    const float* Q     = (const float*)d_in[0];
    const float* K     = (const float*)d_in[1];
    const float* wq    = (const float*)d_in[2];
    const float* bq    = (const float*)d_in[3];
    const float* wk    = (const float*)d_in[4];
    const float* bk    = (const float*)d_in[5];
    const float* wv    = (const float*)d_in[6];
    const float* bv    = (const float*)d_in[7];
    const float* wc    = (const float*)d_in[8];
    const float* bc    = (const float*)d_in[9];
    const float* gq    = (const float*)d_in[10];
    const float* betaq = (const float*)d_in[11];
    const float* gk    = (const float*)d_in[12];
    const float* betak = (const float*)d_in[13];
    const float* g0    = (const float*)d_in[14];
    const float* beta0 = (const float*)d_in[15];
    float* out = (float*)d_out;

    float* O1p;
    cudaGetSymbolAddress((void**)&O1p, g_O1);

    const int PROJ_SMEM = 3 * 2 * 128 * RS * 4;      // 61440
    const int FIN_SMEM  = 2 * 2 * 256 * RS * 4;      // 81920
    const int ATTN_SMEM = 2 * ASTG * 64 * BSTU * 4;  // 73728

    cudaFuncSetAttribute(gemm_proj,  cudaFuncAttributeMaxDynamicSharedMemorySize, PROJ_SMEM);
    cudaFuncSetAttribute(gemm_final, cudaFuncAttributeMaxDynamicSharedMemorySize, FIN_SMEM);
    cudaFuncSetAttribute(attn_mma,   cudaFuncAttributeMaxDynamicSharedMemorySize, ATTN_SMEM);

    // 1. weights->bf16 + Q/K input stats
    prep_kernel<<<768, 256>>>(Q, K, wq, wk, wv, wc);
    // 2. normed inputs -> bf16 (stats folded in)
    norm_qk<<<2048, 256>>>(Q, K, gq, betaq, gk, betak);
    // 3. Q/K/V projections, one launch
    gemm_proj<<<dim3(12, 64), 256, PROJ_SMEM>>>(bq, bk, bv);
    // 4. attention + residual + fused O1 stats
    attn_mma<<<dim3(SS/128, NHH, BB), 128, ATTN_SMEM>>>(Q, O1p);
    // 5. norm O1 -> bf16 hi/lo (stats from attention partials)
    norm_o1<<<1024, 256>>>(O1p, g0, beta0);
    // 6. out = O1 + relu(norm(O1) @ wc^T + bc)
    gemm_final<<<dim3(4, 64), 256, FIN_SMEM>>>(bc, out, O1p);
}

// round 14
// speedup vs baseline: 1.1430x; 1.0191x over previous
#include <cuda_runtime.h>
#include <cuda_bf16.h>
#include <cstdint>

#define BB   4
#define SS   2048
#define SKK  2048
#define HH   512
#define NHH  8
#define DSS  64
#define MTOT (BB*SS)            // 8192
#define BATCH_ELEMS (SS*HH)     // 1048576
#define NPART 64
#define EPSN 1e-5f
#define ATTN_SCALE 0.044194173824159216f   // 1/sqrt(512)
#define LOG2E 1.4426950408889634f

#define RS   20   // gemm smem row stride (uints) = 40 bf16 -> ldmatrix conflict-free
#define BSTU 36   // attn smem row stride (uints) = 72 bf16 -> conflict-free
#define ASTG 4    // attention pipeline stages

// ---------------- scratch (static device memory; no allocations) ----------------
__device__ __nv_bfloat16 g_Xq[MTOT*HH];    // normed Q input, bf16
__device__ __nv_bfloat16 g_Xk[MTOT*HH];    // normed K input, bf16
__device__ __nv_bfloat16 g_XoH[MTOT*HH];   // normed O1, bf16 hi
__device__ __nv_bfloat16 g_XoL[MTOT*HH];   // normed O1, bf16 lo
__device__ __nv_bfloat16 g_pQh[MTOT*HH];   // pQ * ATTN_SCALE * log2(e), [m][d]
__device__ __nv_bfloat16 g_pKh[MTOT*HH];   // [m][d]
__device__ __nv_bfloat16 g_pVh[MTOT*HH];   // [m][d]
__device__ float g_O1[MTOT*HH];
__device__ __nv_bfloat16 g_wqh[HH*HH], g_wkh[HH*HH], g_wvh[HH*HH];
__device__ __nv_bfloat16 g_wch[HH*HH], g_wcl[HH*HH];
__device__ float g_part[2][BB][NPART][2];   // Q/K input partial sums
__device__ float g_apart[BB][NHH*16][2];    // O1 partial sums (from attention blocks)

// ---------------- helpers ----------------
__device__ __forceinline__ unsigned packbf(float lo, float hi){
    unsigned r; asm("cvt.rn.bf16x2.f32 %0, %1, %2;" : "=r"(r) : "f"(hi), "f"(lo)); return r;
}
__device__ __forceinline__ unsigned ex2b2(unsigned x){
    unsigned y; asm("ex2.approx.ftz.bf16x2 %0, %1;" : "=r"(y) : "r"(x)); return y;
}
__device__ __forceinline__ void mma_bf16(float c[4], const unsigned a[4], const unsigned b[2]){
    asm volatile("mma.sync.aligned.m16n8k16.row.col.f32.bf16.bf16.f32 "
        "{%0,%1,%2,%3}, {%4,%5,%6,%7}, {%8,%9}, {%0,%1,%2,%3};"
        : "+f"(c[0]), "+f"(c[1]), "+f"(c[2]), "+f"(c[3])
        : "r"(a[0]), "r"(a[1]), "r"(a[2]), "r"(a[3]), "r"(b[0]), "r"(b[1]));
}
__device__ __forceinline__ void ldm_x4(unsigned r[4], uint32_t addr){
    asm volatile("ldmatrix.sync.aligned.m8n8.x4.shared.b16 {%0,%1,%2,%3}, [%4];"
        : "=r"(r[0]), "=r"(r[1]), "=r"(r[2]), "=r"(r[3]) : "r"(addr));
}
__device__ __forceinline__ void ldm_x4_t(unsigned r[4], uint32_t addr){
    asm volatile("ldmatrix.sync.aligned.m8n8.x4.trans.shared.b16 {%0,%1,%2,%3}, [%4];"
        : "=r"(r[0]), "=r"(r[1]), "=r"(r[2]), "=r"(r[3]) : "r"(addr));
}
__device__ __forceinline__ void cp16(uint32_t dst, const void* src){
    asm volatile("cp.async.ca.shared.global [%0], [%1], 16;" :: "r"(dst), "l"(src));
}
__device__ __forceinline__ void cp_commit(){
    asm volatile("cp.async.commit_group;");
}

// ---------------- prep: convert weights to bf16 + input stats, one launch ----------------
__global__ void __launch_bounds__(256) prep_kernel(
    const float* __restrict__ Q, const float* __restrict__ K,
    const float* __restrict__ wq, const float* __restrict__ wk,
    const float* __restrict__ wv, const float* __restrict__ wc)
{
    __shared__ float ss[8], sq[8];
    const int bx = blockIdx.x, t = threadIdx.x;
    if (bx < 256){
        const int i = bx * 256 + t;   // quad index < 65536
        {
            float4 v = ((const float4*)wq)[i];
            ((uint2*)(unsigned*)g_wqh)[i] = make_uint2(packbf(v.x, v.y), packbf(v.z, v.w));
        }
        {
            float4 v = ((const float4*)wk)[i];
            ((uint2*)(unsigned*)g_wkh)[i] = make_uint2(packbf(v.x, v.y), packbf(v.z, v.w));
        }
        {
            float4 v = ((const float4*)wv)[i];
            ((uint2*)(unsigned*)g_wvh)[i] = make_uint2(packbf(v.x, v.y), packbf(v.z, v.w));
        }
        {
            float4 v = ((const float4*)wc)[i];
            unsigned h0 = packbf(v.x, v.y), h1 = packbf(v.z, v.w);
            ((uint2*)(unsigned*)g_wch)[i] = make_uint2(h0, h1);
            float hx = __uint_as_float(h0 << 16), hy = __uint_as_float(h0 & 0xffff0000u);
            float hz = __uint_as_float(h1 << 16), hw = __uint_as_float(h1 & 0xffff0000u);
            ((uint2*)(unsigned*)g_wcl)[i] = make_uint2(packbf(v.x - hx, v.y - hy), packbf(v.z - hz, v.w - hw));
        }
        return;
    }
    const int slot = (bx >= 512) ? 1 : 0;
    const int idx = bx - 256 - slot*256;
    const int batch = idx >> 6, part = idx & 63;
    const float* x = slot ? K : Q;
    const float4* p = (const float4*)(x + (size_t)batch*BATCH_ELEMS + (size_t)part*(BATCH_ELEMS/NPART));
    float s = 0.f, q = 0.f;
#pragma unroll
    for (int i = 0; i < 16; i++){
        float4 v = p[t + 256*i];
        s += v.x + v.y + v.z + v.w;
        q += v.x*v.x + v.y*v.y + v.z*v.z + v.w*v.w;
    }
#pragma unroll
    for (int off = 16; off; off >>= 1){
        s += __shfl_xor_sync(0xffffffffu, s, off);
        q += __shfl_xor_sync(0xffffffffu, q, off);
    }
    const int w = t >> 5;
    if ((t & 31) == 0){ ss[w] = s; sq[w] = q; }
    __syncthreads();
    if (t == 0){
        float S_ = 0.f, Q_ = 0.f;
#pragma unroll
        for (int i = 0; i < 8; i++){ S_ += ss[i]; Q_ += sq[i]; }
        g_part[slot][batch][part][0] = S_;
        g_part[slot][batch][part][1] = Q_;
    }
}

// ---------------- norm Q/K inputs -> bf16 (stats folded in), 4 float4/thread ----------------
__global__ void __launch_bounds__(256) norm_qk(
    const float* __restrict__ Q, const float* __restrict__ K,
    const float* __restrict__ gq, const float* __restrict__ bq,
    const float* __restrict__ gk, const float* __restrict__ bk)
{
    __shared__ float sred[4], smr[2];
    const int tid = threadIdx.x;
    const int slot = (blockIdx.x >= 1024) ? 1 : 0;
    const int base = (blockIdx.x - slot*1024) * 1024 + tid;   // quad index
    const int batch = base >> 18;
    if (tid < 64){
        float s = g_part[slot][batch][tid][0];
        float q = g_part[slot][batch][tid][1];
#pragma unroll
        for (int off = 16; off; off >>= 1){
            s += __shfl_xor_sync(0xffffffffu, s, off);
            q += __shfl_xor_sync(0xffffffffu, q, off);
        }
        if ((tid & 31) == 0){ sred[(tid>>5)*2] = s; sred[(tid>>5)*2+1] = q; }
    }
    __syncthreads();
    if (tid == 0){
        float S = sred[0] + sred[2], Qa = sred[1] + sred[3];
        float mean = S * (1.0f/(float)BATCH_ELEMS);
        float var  = Qa * (1.0f/(float)BATCH_ELEMS) - mean*mean;
        smr[0] = mean; smr[1] = rsqrtf(var + EPSN);
    }
    __syncthreads();
    const float mean = smr[0], rstd = smr[1];

    const float* X = slot ? K : Q;
    const float* gg = slot ? gk : gq;
    const float* bb = slot ? bk : bq;
    unsigned* outHi = slot ? (unsigned*)g_Xk : (unsigned*)g_Xq;
#pragma unroll
    for (int it = 0; it < 4; it++){
        const int i = base + 256*it;
        const int kq = i & 127;
        const float4 x = ((const float4*)X)[i];
        const float4 g4 = ((const float4*)gg)[kq];
        const float4 b4 = ((const float4*)bb)[kq];
        float4 y;
        y.x = (x.x - mean)*rstd*g4.x + b4.x;
        y.y = (x.y - mean)*rstd*g4.y + b4.y;
        y.z = (x.z - mean)*rstd*g4.z + b4.z;
        y.w = (x.w - mean)*rstd*g4.w + b4.w;
        ((uint2*)outHi)[i] = make_uint2(packbf(y.x, y.y), packbf(y.z, y.w));
    }
}

// ---------------- norm O1 -> bf16 hi/lo (stats from attention partials) ----------------
__global__ void __launch_bounds__(256) norm_o1(
    const float* __restrict__ O1,
    const float* __restrict__ g0, const float* __restrict__ beta0)
{
    __shared__ float sred[8], smr[2];
    const int tid = threadIdx.x;
    const int base = blockIdx.x * 1024 + tid;
    const int batch = base >> 18;
    if (tid < 128){
        float s = g_apart[batch][tid][0];
        float q = g_apart[batch][tid][1];
#pragma unroll
        for (int off = 16; off; off >>= 1){
            s += __shfl_xor_sync(0xffffffffu, s, off);
            q += __shfl_xor_sync(0xffffffffu, q, off);
        }
        if ((tid & 31) == 0){ sred[(tid>>5)*2] = s; sred[(tid>>5)*2+1] = q; }
    }
    __syncthreads();
    if (tid == 0){
        float S = sred[0] + sred[2] + sred[4] + sred[6];
        float Qa = sred[1] + sred[3] + sred[5] + sred[7];
        float mean = S * (1.0f/(float)BATCH_ELEMS);
        float var  = Qa * (1.0f/(float)BATCH_ELEMS) - mean*mean;
        smr[0] = mean; smr[1] = rsqrtf(var + EPSN);
    }
    __syncthreads();
    const float mean = smr[0], rstd = smr[1];

#pragma unroll
    for (int it = 0; it < 4; it++){
        const int i = base + 256*it;
        const int kq = i & 127;
        const float4 x = ((const float4*)O1)[i];
        const float4 g4 = ((const float4*)g0)[kq];
        const float4 b4 = ((const float4*)beta0)[kq];
        float4 y;
        y.x = (x.x - mean)*rstd*g4.x + b4.x;
        y.y = (x.y - mean)*rstd*g4.y + b4.y;
        y.z = (x.z - mean)*rstd*g4.z + b4.z;
        y.w = (x.w - mean)*rstd*g4.w + b4.w;
        unsigned h0 = packbf(y.x, y.y), h1 = packbf(y.z, y.w);
        ((uint2*)(unsigned*)g_XoH)[i] = make_uint2(h0, h1);
        float hx = __uint_as_float(h0 << 16), hy = __uint_as_float(h0 & 0xffff0000u);
        float hz = __uint_as_float(h1 << 16), hw = __uint_as_float(h1 & 0xffff0000u);
        ((uint2*)(unsigned*)g_XoL)[i] = make_uint2(packbf(y.x - hx, y.y - hy), packbf(y.z - hz, y.w - hw));
    }
}

// ---------------- fused Q/K/V projection GEMM, 3-stage cp.async ----------------
__global__ void __launch_bounds__(256, 2) gemm_proj(
    const float* __restrict__ bq, const float* __restrict__ bk, const float* __restrict__ bv)
{
    extern __shared__ unsigned smu[];
    unsigned* As = smu;                      // [3][128][RS]
    unsigned* Ws = smu + 3*128*RS;
    const uint32_t sA = (uint32_t)__cvta_generic_to_shared(As);
    const uint32_t sW = (uint32_t)__cvta_generic_to_shared(Ws);

    const int tid  = threadIdx.x;
    const int lane = tid & 31, w = tid >> 5;
    const int g = lane >> 2, t4 = lane & 3;
    const int which = blockIdx.x >> 2;
    const __nv_bfloat16* A = (which == 0) ? g_Xq : g_Xk;
    const __nv_bfloat16* W = (which == 0) ? g_wqh : (which == 1) ? g_wkh : g_wvh;
    const float* biasp = (which == 0) ? bq : (which == 1) ? bk : bv;
    __nv_bfloat16* outp = (which == 0) ? g_pQh : (which == 1) ? g_pKh : g_pVh;
    const float scl = (which == 0) ? (ATTN_SCALE * LOG2E) : 1.0f;
    const int n0 = (blockIdx.x & 3) * 128;
    const int m0 = blockIdx.y * 128;

    const int mw = w >> 1, nw = w & 1;
    const int mrow = mw * 32, nrow = nw * 64;

    float acc[2][8][4];
#pragma unroll
    for (int i = 0; i < 2; i++)
#pragma unroll
        for (int j = 0; j < 8; j++)
#pragma unroll
            for (int r = 0; r < 4; r++) acc[i][j][r] = 0.f;

    const int aRow  = lane & 15;
    const int aColU = (lane >> 4) << 2;
    const int bRow  = ((lane >> 4) << 3) + (lane & 7);
    const int bColU = ((lane >> 3) & 1) << 2;

    auto loadTile = [&](int kt, int s){
        const int kb = kt * 32;
#pragma unroll
        for (int i = 0; i < 2; i++){
            const int c = tid + 256*i;
            const int row = c >> 2, seg = c & 3;
            cp16(sA + (uint32_t)(s*128*RS + row*RS + seg*4)*4, A + (size_t)(m0 + row)*HH + kb + seg*8);
            cp16(sW + (uint32_t)(s*128*RS + row*RS + seg*4)*4, W + (size_t)(n0 + row)*HH + kb + seg*8);
        }
    };

    loadTile(0, 0); cp_commit();
    loadTile(1, 1); cp_commit();

    for (int kt = 0; kt < 16; kt++){
        const int s = kt % 3;
        if (kt + 2 < 16) loadTile(kt + 2, (kt + 2) % 3);
        cp_commit();
        asm volatile("cp.async.wait_group 2;");
        __syncthreads();

        const uint32_t aBase = sA + (uint32_t)(s*128*RS)*4;
        const uint32_t wBase = sW + (uint32_t)(s*128*RS)*4;
#pragma unroll
        for (int ks = 0; ks < 2; ks++){
            unsigned ah[2][4];
#pragma unroll
            for (int i = 0; i < 2; i++)
                ldm_x4(ah[i], aBase + (uint32_t)((mrow + i*16 + aRow)*RS + ks*8 + aColU)*4);
            unsigned bh[4][4];
#pragma unroll
            for (int jj = 0; jj < 4; jj++)
                ldm_x4(bh[jj], wBase + (uint32_t)((nrow + jj*16 + bRow)*RS + ks*8 + bColU)*4);
#pragma unroll
            for (int i = 0; i < 2; i++)
#pragma unroll
                for (int jj = 0; jj < 4; jj++){
                    mma_bf16(acc[i][2*jj],   ah[i], bh[jj]);
                    mma_bf16(acc[i][2*jj+1], ah[i], bh[jj] + 2);
                }
        }
        __syncthreads();
    }

#pragma unroll
    for (int i = 0; i < 2; i++){
#pragma unroll
        for (int j = 0; j < 8; j++){
            const int col = n0 + nrow + j*8 + 2*t4;
            const float2 bs = *(const float2*)&biasp[col];
#pragma unroll
            for (int hh = 0; hh < 2; hh++){
                const int row = m0 + mrow + i*16 + g + 8*hh;
                float cx = acc[i][j][2*hh]   + bs.x;
                float cy = acc[i][j][2*hh+1] + bs.y;
                ((unsigned*)outp)[(size_t)row*(HH/2) + (col >> 1)] = packbf(cx*scl, cy*scl);
            }
        }
    }
}

// ---------------- final GEMM: out = res + relu(A.W^T + bias), 3-term bf16 split ----------------
// 2-stage pipeline, 2 blocks/SM -> 256 blocks fit one wave.
__global__ void __launch_bounds__(256, 2) gemm_final(
    const float* __restrict__ bc, float* __restrict__ out, const float* __restrict__ res)
{
    extern __shared__ unsigned smu[];
    const int AROWS = 256;
    unsigned* As = smu;                      // [2][256][RS]
    unsigned* Ws = smu + 2*AROWS*RS;
    const uint32_t sA = (uint32_t)__cvta_generic_to_shared(As);
    const uint32_t sW = (uint32_t)__cvta_generic_to_shared(Ws);

    const int tid  = threadIdx.x;
    const int lane = tid & 31, w = tid >> 5;
    const int g = lane >> 2, t4 = lane & 3;
    const int n0 = (int)blockIdx.x * 128;
    const int m0 = blockIdx.y * 128;

    const int mw = w >> 1, nw = w & 1;
    const int mrow = mw * 32, nrow = nw * 64;

    float acc[2][8][4];
#pragma unroll
    for (int i = 0; i < 2; i++)
#pragma unroll
        for (int j = 0; j < 8; j++)
#pragma unroll
            for (int r = 0; r < 4; r++) acc[i][j][r] = 0.f;

    const int aRow  = lane & 15;
    const int aColU = (lane >> 4) << 2;
    const int bRow  = ((lane >> 4) << 3) + (lane & 7);
    const int bColU = ((lane >> 3) & 1) << 2;

    auto loadTile = [&](int kt, int s){
        const int kb = kt * 32;
#pragma unroll
        for (int i = 0; i < 4; i++){
            const int c = tid + 256*i;
            const int row = c >> 2, seg = c & 3;
            const __nv_bfloat16* srcA = (row >= 128)
                ? (g_XoL + (size_t)(m0 + row - 128)*HH + kb + seg*8)
                : (g_XoH + (size_t)(m0 + row)*HH + kb + seg*8);
            cp16(sA + (uint32_t)(s*AROWS*RS + row*RS + seg*4)*4, srcA);
            const __nv_bfloat16* srcW = (row >= 128)
                ? (g_wcl + (size_t)(n0 + row - 128)*HH + kb + seg*8)
                : (g_wch + (size_t)(n0 + row)*HH + kb + seg*8);
            cp16(sW + (uint32_t)(s*AROWS*RS + row*RS + seg*4)*4, srcW);
        }
    };

    loadTile(0, 0); cp_commit();
    loadTile(1, 1); cp_commit();

    for (int kt = 0; kt < 16; kt++){
        const int s = kt & 1;
        if (kt + 1 < 16) asm volatile("cp.async.wait_group 1;");
        else             asm volatile("cp.async.wait_group 0;");
        __syncthreads();

        const uint32_t aBase = sA + (uint32_t)(s*AROWS*RS)*4;
        const uint32_t wBase = sW + (uint32_t)(s*AROWS*RS)*4;
#pragma unroll
        for (int ks = 0; ks < 2; ks++){
            unsigned ah[2][4], alo_[2][4];
#pragma unroll
            for (int i = 0; i < 2; i++){
                ldm_x4(ah[i],   aBase + (uint32_t)((mrow + i*16 + aRow)*RS + ks*8 + aColU)*4);
                ldm_x4(alo_[i], aBase + (uint32_t)((128 + mrow + i*16 + aRow)*RS + ks*8 + aColU)*4);
            }
#pragma unroll
            for (int jj = 0; jj < 4; jj++){
                unsigned bh[4], bl[4];
                ldm_x4(bh, wBase + (uint32_t)((nrow + jj*16 + bRow)*RS + ks*8 + bColU)*4);
                ldm_x4(bl, wBase + (uint32_t)((128 + nrow + jj*16 + bRow)*RS + ks*8 + bColU)*4);
#pragma unroll
                for (int i = 0; i < 2; i++){
                    mma_bf16(acc[i][2*jj],   ah[i], bh);
                    mma_bf16(acc[i][2*jj+1], ah[i], bh + 2);
                    mma_bf16(acc[i][2*jj],   ah[i], bl);
                    mma_bf16(acc[i][2*jj+1], ah[i], bl + 2);
                    mma_bf16(acc[i][2*jj],   alo_[i], bh);
                    mma_bf16(acc[i][2*jj+1], alo_[i], bh + 2);
                }
            }
        }
        __syncthreads();
        if (kt + 2 < 16){ loadTile(kt + 2, s); cp_commit(); }
    }

#pragma unroll
    for (int i = 0; i < 2; i++){
#pragma unroll
        for (int j = 0; j < 8; j++){
            const int col = n0 + nrow + j*8 + 2*t4;
            const float2 bs = *(const float2*)&bc[col];
#pragma unroll
            for (int hh = 0; hh < 2; hh++){
                const int row = m0 + mrow + i*16 + g + 8*hh;
                float cx = acc[i][j][2*hh]   + bs.x;
                float cy = acc[i][j][2*hh+1] + bs.y;
                const float2 rv = *(const float2*)&res[(size_t)row*HH + col];
                float2 o;
                o.x = rv.x + fmaxf(cx, 0.f);
                o.y = rv.y + fmaxf(cy, 0.f);
                *(float2*)&out[(size_t)row*HH + col] = o;
            }
        }
    }
}

// ---------------- flash attention: bf16x2 ex2 + l via ones-MMA ----------------
// No-max softmax: scores packed to bf16x2, ONE ex2.approx.ftz.bf16x2 per pair yields the
// PV A-frag word directly (MUFU ops halved). Row sums l computed by an extra N=8 MMA
// against an all-ones B-frag (exact, no FADD chain, no shuffles).
// 128-thr blocks, 2 blocks/SM; warp owns 32 q-rows x 64 keys; 4-stage cp.async,
// 1 sync per 2 key-tiles.
__global__ void __launch_bounds__(128, 2) attn_mma(
    const float* __restrict__ Qraw, float* __restrict__ O1)
{
    extern __shared__ unsigned smu[];
    unsigned* KsBase = smu;                  // [ASTG][64][BSTU]
    unsigned* VsBase = smu + ASTG*64*BSTU;   // [ASTG][64][BSTU]
    unsigned* Qs     = smu;                  // staging alias
    __shared__ float sb2[4][2];

    const int tid  = threadIdx.x;
    const int lane = tid & 31, w = tid >> 5;
    const int g = lane >> 2, t4 = lane & 3;

    const int qt = blockIdx.x, h = blockIdx.y, b = blockIdx.z;
    const int hoff = h * DSS;
    const int qrow0 = b * SS + qt * 128;

    const uint32_t smemK = (uint32_t)__cvta_generic_to_shared(KsBase);
    const uint32_t smemV = (uint32_t)__cvta_generic_to_shared(VsBase);
    const uint32_t smemQ = (uint32_t)__cvta_generic_to_shared(Qs);

    {
#pragma unroll
        for (int i = 0; i < 8; i++){
            const int ch = tid + 128*i;
            const int row = ch >> 3, c = ch & 7;
            cp16(smemQ + (uint32_t)(row*BSTU + c*4)*4, g_pQh + (size_t)(qrow0 + row)*HH + hoff + c*8);
        }
        cp_commit();
        asm volatile("cp.async.wait_group 0;");
    }
    __syncthreads();

    unsigned q[2][4][4];
    {
        const int aRow = lane & 15, aColU = (lane >> 4) << 2;
#pragma unroll
        for (int hh = 0; hh < 2; hh++)
#pragma unroll
            for (int kc = 0; kc < 4; kc++)
                ldm_x4(q[hh][kc], smemQ + (uint32_t)((w*32 + hh*16 + aRow)*BSTU + kc*8 + aColU)*4);
    }
    __syncthreads();

    float o[2][8][4];
#pragma unroll
    for (int hh = 0; hh < 2; hh++)
#pragma unroll
        for (int j = 0; j < 8; j++)
#pragma unroll
            for (int r = 0; r < 4; r++) o[hh][j][r] = 0.f;
    float lacc[2][4];   // row-sum accumulators via ones-MMA (lanes 0/2 hold exact row sums)
#pragma unroll
    for (int hh = 0; hh < 2; hh++)
#pragma unroll
        for (int r = 0; r < 4; r++) lacc[hh][r] = 0.f;

    const unsigned ones2[2] = {0x3F803F80u, 0x3F803F80u};   // bf16 1.0 x2

    const __nv_bfloat16* gK0 = g_pKh + ((size_t)b * SKK) * HH + hoff;
    const __nv_bfloat16* gV0 = g_pVh + ((size_t)b * SKK) * HH + hoff;

    auto loadKV = [&](int t, int s){
        const __nv_bfloat16* gK = gK0 + (size_t)t*64*HH;
        const __nv_bfloat16* gV = gV0 + (size_t)t*64*HH;
#pragma unroll
        for (int i = 0; i < 4; i++){
            const int ch = tid + 128*i;
            const int row = ch >> 3, c = ch & 7;
            cp16(smemK + (uint32_t)(s*64*BSTU + row*BSTU + c*4)*4, gK + (size_t)row*HH + c*8);
            cp16(smemV + (uint32_t)(s*64*BSTU + row*BSTU + c*4)*4, gV + (size_t)row*HH + c*8);
        }
    };

    loadKV(0, 0); cp_commit();
    loadKV(1, 1); cp_commit();

    const int kRow  = lane & 7;
    const int kColU = (lane >> 3) << 2;
    const int vRow  = lane & 15;
    const int vColU = (lane >> 4) << 2;

    for (int tt = 0; tt < SKK/64; tt += 2){
        asm volatile("cp.async.wait_group 0;");
        __syncthreads();
        if (tt + 2 < SKK/64){ loadKV(tt + 2, (tt + 2) & (ASTG-1)); cp_commit(); }
        if (tt + 3 < SKK/64){ loadKV(tt + 3, (tt + 3) & (ASTG-1)); cp_commit(); }

#pragma unroll
        for (int u = 0; u < 2; u++){
            const int s = (tt + u) & (ASTG-1);
            const uint32_t kBase = smemK + (uint32_t)(s*64*BSTU)*4;
            const uint32_t vBase = smemV + (uint32_t)(s*64*BSTU)*4;

            // ---- S = Q K^T for both 16-row halves (K frags loaded once)
            float sacc[2][8][4];
#pragma unroll
            for (int hh = 0; hh < 2; hh++)
#pragma unroll
                for (int j = 0; j < 8; j++)
#pragma unroll
                    for (int r = 0; r < 4; r++) sacc[hh][j][r] = 0.f;

#pragma unroll
            for (int j = 0; j < 8; j++){
                unsigned kb0[4], kb1[4];
                ldm_x4(kb0, kBase + (uint32_t)((j*8 + kRow)*BSTU + kColU)*4);
                ldm_x4(kb1, kBase + (uint32_t)((j*8 + kRow)*BSTU + 16 + kColU)*4);
#pragma unroll
                for (int hh = 0; hh < 2; hh++){
                    mma_bf16(sacc[hh][j], q[hh][0], kb0);
                    mma_bf16(sacc[hh][j], q[hh][1], kb0 + 2);
                    mma_bf16(sacc[hh][j], q[hh][2], kb1);
                    mma_bf16(sacc[hh][j], q[hh][3], kb1 + 2);
                }
            }

            // ---- P = 2^s via bf16x2 ex2 (pack scores, then one ex2 per pair)
            unsigned pr[2][8][2];
#pragma unroll
            for (int hh = 0; hh < 2; hh++)
#pragma unroll
                for (int j = 0; j < 8; j++){
                    pr[hh][j][0] = ex2b2(packbf(sacc[hh][j][0], sacc[hh][j][1]));
                    pr[hh][j][1] = ex2b2(packbf(sacc[hh][j][2], sacc[hh][j][3]));
                }

            // ---- O += P V, l += P . 1 (V frags loaded once per kg/jp)
#pragma unroll
            for (int kg = 0; kg < 4; kg++){
                unsigned pa[2][4];
#pragma unroll
                for (int hh = 0; hh < 2; hh++){
                    pa[hh][0] = pr[hh][2*kg  ][0];
                    pa[hh][1] = pr[hh][2*kg  ][1];
                    pa[hh][2] = pr[hh][2*kg+1][0];
                    pa[hh][3] = pr[hh][2*kg+1][1];
                    mma_bf16(lacc[hh], pa[hh], ones2);
                }
#pragma unroll
                for (int jp = 0; jp < 4; jp++){
                    unsigned vb[4];
                    ldm_x4_t(vb, vBase + (uint32_t)((kg*16 + vRow)*BSTU + jp*8 + vColU)*4);
#pragma unroll
                    for (int hh = 0; hh < 2; hh++){
                        mma_bf16(o[hh][2*jp],   pa[hh], vb);
                        mma_bf16(o[hh][2*jp+1], pa[hh], vb + 2);
                    }
                }
            }
        }
    }

    // ---- l is exact in lanes 0 (row g) and 2 (row g+8) of each lacc
    float lv[4];
    lv[0] = lacc[0][0]; lv[1] = lacc[0][2];
    lv[2] = lacc[1][0]; lv[3] = lacc[1][2];

    // ---- epilogue: O1 = Qraw + O / l, with fused sum/sumsq for set-norm stats
    float s1 = 0.f, s2 = 0.f;
#pragma unroll
    for (int hh = 0; hh < 2; hh++){
        const float inv0 = 1.0f / lv[hh*2], inv1 = 1.0f / lv[hh*2+1];
        const int row0 = qrow0 + w*32 + hh*16 + g;
#pragma unroll
        for (int jd = 0; jd < 8; jd++){
            const int col = hoff + jd*8 + 2*t4;
            {
                const float2 qv = *(const float2*)&Qraw[(size_t)row0*HH + col];
                float2 ov; ov.x = qv.x + o[hh][jd][0]*inv0; ov.y = qv.y + o[hh][jd][1]*inv0;
                *(float2*)&O1[(size_t)row0*HH + col] = ov;
                s1 += ov.x + ov.y; s2 += ov.x*ov.x + ov.y*ov.y;
            }
            {
                const float2 qv = *(const float2*)&Qraw[(size_t)(row0+8)*HH + col];
                float2 ov; ov.x = qv.x + o[hh][jd][2]*inv1; ov.y = qv.y + o[hh][jd][3]*inv1;
                *(float2*)&O1[(size_t)(row0+8)*HH + col] = ov;
                s1 += ov.x + ov.y; s2 += ov.x*ov.x + ov.y*ov.y;
            }
        }
    }
#pragma unroll
    for (int off = 16; off; off >>= 1){
        s1 += __shfl_xor_sync(0xffffffffu, s1, off);
        s2 += __shfl_xor_sync(0xffffffffu, s2, off);
    }
    if (lane == 0){ sb2[w][0] = s1; sb2[w][1] = s2; }
    __syncthreads();
    if (tid == 0){
        float a = 0.f, c = 0.f;
#pragma unroll
        for (int i = 0; i < 4; i++){ a += sb2[i][0]; c += sb2[i][1]; }
        g_apart[b][h*16 + qt][0] = a;
        g_apart[b][h*16 + qt][1] = c;
    }
}

// ---------------- launcher ----------------
extern "C" void kernel_launch(void* const* d_in, const int* in_sizes, int n_in,
                              void* d_out, int out_size)
{
    (void)in_sizes; (void)n_in; (void)out_size;
    const float* Q     = (const float*)d_in[0];
    const float* K     = (const float*)d_in[1];
    const float* wq    = (const float*)d_in[2];
    const float* bq    = (const float*)d_in[3];
    const float* wk    = (const float*)d_in[4];
    const float* bk    = (const float*)d_in[5];
    const float* wv    = (const float*)d_in[6];
    const float* bv    = (const float*)d_in[7];
    const float* wc    = (const float*)d_in[8];
    const float* bc    = (const float*)d_in[9];
    const float* gq    = (const float*)d_in[10];
    const float* betaq = (const float*)d_in[11];
    const float* gk    = (const float*)d_in[12];
    const float* betak = (const float*)d_in[13];
    const float* g0    = (const float*)d_in[14];
    const float* beta0 = (const float*)d_in[15];
    float* out = (float*)d_out;

    float* O1p;
    cudaGetSymbolAddress((void**)&O1p, g_O1);

    const int PROJ_SMEM = 3 * 2 * 128 * RS * 4;      // 61440
    const int FIN_SMEM  = 2 * 2 * 256 * RS * 4;      // 81920
    const int ATTN_SMEM = 2 * ASTG * 64 * BSTU * 4;  // 73728

    cudaFuncSetAttribute(gemm_proj,  cudaFuncAttributeMaxDynamicSharedMemorySize, PROJ_SMEM);
    cudaFuncSetAttribute(gemm_final, cudaFuncAttributeMaxDynamicSharedMemorySize, FIN_SMEM);
    cudaFuncSetAttribute(attn_mma,   cudaFuncAttributeMaxDynamicSharedMemorySize, ATTN_SMEM);

    // 1. weights->bf16 + Q/K input stats
    prep_kernel<<<768, 256>>>(Q, K, wq, wk, wv, wc);
    // 2. normed inputs -> bf16 (stats folded in)
    norm_qk<<<2048, 256>>>(Q, K, gq, betaq, gk, betak);
    // 3. Q/K/V projections, one launch
    gemm_proj<<<dim3(12, 64), 256, PROJ_SMEM>>>(bq, bk, bv);
    // 4. attention + residual + fused O1 stats
    attn_mma<<<dim3(SS/128, NHH, BB), 128, ATTN_SMEM>>>(Q, O1p);
    // 5. norm O1 -> bf16 hi/lo (stats from attention partials)
    norm_o1<<<1024, 256>>>(O1p, g0, beta0);
    // 6. out = O1 + relu(norm(O1) @ wc^T + bc)
    gemm_final<<<dim3(4, 64), 256, FIN_SMEM>>>(bc, out, O1p);
}